// round 3
// baseline (speedup 1.0000x reference)
#include <cuda_runtime.h>

// Problem constants
namespace {
constexpr int NB = 64;     // batch
constexpr int NS = 1024;   // sequence length
constexpr int NI = 512;    // input dim
constexpr int NH = 2048;   // hidden dim
constexpr int NO = 512;    // output dim
constexpr int BH = NB * NH;      // 131072 state elements
constexpr int SK = 4;            // split-K factor for the step GEMM
constexpr int KC = NH / SK;      // 512 K-chunk
constexpr int GB = 128;          // persistent grid blocks (<=148 SMs, co-resident)
constexpr int UPB = BH / GB;     // 1024 update elements per block
}

// Scratch (static device allocations — no cudaMalloc allowed)
__device__ float g_xw[(size_t)NS * NB * NH];      // [t][b][h] input projection
__device__ float g_hid_fb[(size_t)NB * NS * NH];  // fallback hidden storage
__device__ float g_part[SK * BH];                 // split-K partials
__device__ float g_h[BH];                         // current hidden state [b][h]
__device__ float g_sigh[2][BH];                   // ping-pong sigmoid(h)  [b][h]

// grid-barrier state (must return to {0,0} at end of every launch)
__device__ unsigned g_count;
__device__ unsigned g_flag;

// ---------------- f32x2 packed math helpers (sm_100+) ----------------
__device__ __forceinline__ unsigned long long pack2(float x, float y) {
    unsigned long long r;
    asm("mov.b64 %0, {%1,%2};" : "=l"(r)
        : "r"(__float_as_uint(x)), "r"(__float_as_uint(y)));
    return r;
}
__device__ __forceinline__ unsigned long long dup2(float x) {
    unsigned long long r;
    unsigned u = __float_as_uint(x);
    asm("mov.b64 %0, {%1,%2};" : "=l"(r) : "r"(u), "r"(u));
    return r;
}
__device__ __forceinline__ unsigned long long fma2(unsigned long long a,
                                                   unsigned long long b,
                                                   unsigned long long c) {
    unsigned long long d;
    asm("fma.rn.f32x2 %0, %1, %2, %3;" : "=l"(d) : "l"(a), "l"(b), "l"(c));
    return d;
}
__device__ __forceinline__ float2 unpack2(unsigned long long v) {
    unsigned lo, hi;
    asm("mov.b64 {%0,%1}, %2;" : "=r"(lo), "=r"(hi) : "l"(v));
    return make_float2(__uint_as_float(lo), __uint_as_float(hi));
}
__device__ __forceinline__ float sigmoidf_(float x) {
    return 1.0f / (1.0f + __expf(-x));
}

// ---------------- software grid barrier (sense reversal) ----------------
// Even number of calls per launch -> g_flag/g_count end at initial 0.
__device__ __forceinline__ void grid_barrier(unsigned want) {
    __syncthreads();
    if (threadIdx.x == 0) {
        unsigned* cnt = &g_count;
        unsigned* flg = &g_flag;
        unsigned old;
        asm volatile("atom.acq_rel.gpu.global.add.u32 %0, [%1], 1;"
                     : "=r"(old) : "l"(cnt) : "memory");
        if (old == (unsigned)(GB - 1)) {
            asm volatile("st.relaxed.gpu.global.u32 [%0], %1;"
                         :: "l"(cnt), "r"(0u) : "memory");
            asm volatile("st.release.gpu.global.u32 [%0], %1;"
                         :: "l"(flg), "r"(want) : "memory");
        } else {
            unsigned v;
            do {
                asm volatile("ld.acquire.gpu.global.u32 %0, [%1];"
                             : "=r"(v) : "l"(flg) : "memory");
            } while (v != want);
        }
    }
    __syncthreads();
}

// ---------------- Persistent recurrence kernel ----------------
// grid = GB(128) blocks x 256 threads, all co-resident (1 block/SM).
// Per step: split-K GEMM (BM=64 all batches, BN=64, SK=4) -> barrier ->
//           fused reduce + Euler update -> barrier.
__global__ void __launch_bounds__(256, 1)
k_recur(const float* __restrict__ h0, const float* __restrict__ Whh,
        const float* __restrict__ noise, float* __restrict__ hidden) {
    __shared__ __align__(16) float As[16][64];
    __shared__ __align__(16) float Ws[16][64];

    const int bx = blockIdx.x;
    const int tid = threadIdx.x;

    // ---- init phase: h = h0, sigh[0] = sigmoid(h0) ----
    {
        int i4 = bx * UPB + tid * 4;
        float4 hv = *(const float4*)(h0 + i4);
        *(float4*)(g_h + i4) = hv;
        float4 sv = make_float4(sigmoidf_(hv.x), sigmoidf_(hv.y),
                                sigmoidf_(hv.z), sigmoidf_(hv.w));
        *(float4*)(g_sigh[0] + i4) = sv;
    }
    unsigned want = 1;
    grid_barrier(want); want ^= 1;

    // GEMM tile assignment
    const int nt = bx & 31;            // n-tile (32 tiles of 64)
    const int sk = bx >> 5;            // split-K id (0..3)
    const int n0 = nt * 64;
    const int kbeg = sk * KC;

    // load-thread mapping: 64 rows x 16 k, one float4 per thread
    const int lm = tid >> 2;           // 0..63
    const int lk = (tid & 3) << 2;     // 0,4,8,12
    const float* Wb = Whh + (size_t)(n0 + lm) * NH + kbeg + lk;

    // compute-thread mapping: 16x16 threads, 4x4 elements each
    const int tx = tid & 15, ty = tid >> 4;
    const int mm = ty << 2, nn = tx << 2;
    float* pout = g_part + (size_t)sk * BH + (size_t)mm * NH + n0 + nn;

    // update-phase index
    const int ui = bx * UPB + tid * 4;
    const int ub = ui >> 11;            // batch
    const int uh = ui & (NH - 1);       // hidden idx
    float* hid_out = hidden + ((size_t)ub * NS) * NH + uh;

    for (int t = 0; t < NS; t++) {
        // ---------------- GEMM phase ----------------
        const float* Ab = g_sigh[t & 1] + (size_t)lm * NH + kbeg + lk;

        unsigned long long acc[4][2];
#pragma unroll
        for (int i = 0; i < 4; i++) { acc[i][0] = 0ull; acc[i][1] = 0ull; }

        float4 ar = *(const float4*)(Ab);
        float4 wr = *(const float4*)(Wb);

        for (int kb = 0; kb < KC; kb += 16) {
            As[lk + 0][lm] = ar.x; As[lk + 1][lm] = ar.y;
            As[lk + 2][lm] = ar.z; As[lk + 3][lm] = ar.w;
            Ws[lk + 0][lm] = wr.x; Ws[lk + 1][lm] = wr.y;
            Ws[lk + 2][lm] = wr.z; Ws[lk + 3][lm] = wr.w;
            __syncthreads();
            if (kb + 16 < KC) {
                ar = *(const float4*)(Ab + kb + 16);
                wr = *(const float4*)(Wb + kb + 16);
            }
#pragma unroll
            for (int k = 0; k < 16; k++) {
                const float4 a  = *(const float4*)(&As[k][mm]);
                const float4 bv = *(const float4*)(&Ws[k][nn]);
                const unsigned long long b0 = pack2(bv.x, bv.y);
                const unsigned long long b1 = pack2(bv.z, bv.w);
                unsigned long long ad;
                ad = dup2(a.x); acc[0][0] = fma2(ad, b0, acc[0][0]); acc[0][1] = fma2(ad, b1, acc[0][1]);
                ad = dup2(a.y); acc[1][0] = fma2(ad, b0, acc[1][0]); acc[1][1] = fma2(ad, b1, acc[1][1]);
                ad = dup2(a.z); acc[2][0] = fma2(ad, b0, acc[2][0]); acc[2][1] = fma2(ad, b1, acc[2][1]);
                ad = dup2(a.w); acc[3][0] = fma2(ad, b0, acc[3][0]); acc[3][1] = fma2(ad, b1, acc[3][1]);
            }
            __syncthreads();
        }
#pragma unroll
        for (int i = 0; i < 4; i++) {
            float2 c0 = unpack2(acc[i][0]);
            float2 c1 = unpack2(acc[i][1]);
            *(float4*)(pout + (size_t)i * NH) = make_float4(c0.x, c0.y, c1.x, c1.y);
        }

        grid_barrier(want); want ^= 1;

        // ---------------- update phase ----------------
        {
            const size_t base = (size_t)t * BH + ui;
            float4 p0 = *(const float4*)(g_part + ui);
            float4 p1 = *(const float4*)(g_part + BH + ui);
            float4 p2 = *(const float4*)(g_part + 2 * BH + ui);
            float4 p3 = *(const float4*)(g_part + 3 * BH + ui);
            float4 xw = *(const float4*)(g_xw + base);
            float4 nz = *(const float4*)(noise + base);
            float4 hp = *(const float4*)(g_h + ui);
            float4 v;
            v.x = 0.9f * hp.x + 0.1f * (p0.x + p1.x + p2.x + p3.x + xw.x) + 0.01f * nz.x;
            v.y = 0.9f * hp.y + 0.1f * (p0.y + p1.y + p2.y + p3.y + xw.y) + 0.01f * nz.y;
            v.z = 0.9f * hp.z + 0.1f * (p0.z + p1.z + p2.z + p3.z + xw.z) + 0.01f * nz.z;
            v.w = 0.9f * hp.w + 0.1f * (p0.w + p1.w + p2.w + p3.w + xw.w) + 0.01f * nz.w;
            *(float4*)(g_h + ui) = v;
            float4 sv = make_float4(sigmoidf_(v.x), sigmoidf_(v.y),
                                    sigmoidf_(v.z), sigmoidf_(v.w));
            *(float4*)(g_sigh[(t + 1) & 1] + ui) = sv;
            *(float4*)(hid_out + (size_t)t * NH) = v;
        }

        grid_barrier(want); want ^= 1;
    }

    // padding barrier -> even total (2050) so g_flag ends at 0
    grid_barrier(want);
}

// ---------------- Kernel: xW[t][b][:] = x[b][t][:] @ W_ih^T ----------------
__global__ void __launch_bounds__(256) k_xw(const float* __restrict__ x,
                                            const float* __restrict__ Wih) {
    __shared__ __align__(16) float As[16][64];
    __shared__ __align__(16) float Ws[16][64];
    const int tid = threadIdx.x;
    const int n0 = blockIdx.x * 64;
    const int t  = blockIdx.y;
    const int lm = tid >> 2;
    const int lk = (tid & 3) << 2;
    const float* arow = x + ((size_t)lm * NS + t) * NI;
    const float* wrow = Wih + (size_t)(n0 + lm) * NI;
    const int tx = tid & 15, ty = tid >> 4;
    const int mm = ty << 2, nn = tx << 2;

    unsigned long long acc[4][2];
#pragma unroll
    for (int i = 0; i < 4; i++) { acc[i][0] = 0ull; acc[i][1] = 0ull; }

    for (int kb = 0; kb < NI; kb += 16) {
        float4 av = *(const float4*)(arow + kb + lk);
        float4 wv = *(const float4*)(wrow + kb + lk);
        As[lk + 0][lm] = av.x; As[lk + 1][lm] = av.y;
        As[lk + 2][lm] = av.z; As[lk + 3][lm] = av.w;
        Ws[lk + 0][lm] = wv.x; Ws[lk + 1][lm] = wv.y;
        Ws[lk + 2][lm] = wv.z; Ws[lk + 3][lm] = wv.w;
        __syncthreads();
#pragma unroll
        for (int k = 0; k < 16; k++) {
            const float4 a  = *(const float4*)(&As[k][mm]);
            const float4 bv = *(const float4*)(&Ws[k][nn]);
            const unsigned long long b0 = pack2(bv.x, bv.y);
            const unsigned long long b1 = pack2(bv.z, bv.w);
            unsigned long long ad;
            ad = dup2(a.x); acc[0][0] = fma2(ad, b0, acc[0][0]); acc[0][1] = fma2(ad, b1, acc[0][1]);
            ad = dup2(a.y); acc[1][0] = fma2(ad, b0, acc[1][0]); acc[1][1] = fma2(ad, b1, acc[1][1]);
            ad = dup2(a.z); acc[2][0] = fma2(ad, b0, acc[2][0]); acc[2][1] = fma2(ad, b1, acc[2][1]);
            ad = dup2(a.w); acc[3][0] = fma2(ad, b0, acc[3][0]); acc[3][1] = fma2(ad, b1, acc[3][1]);
        }
        __syncthreads();
    }
#pragma unroll
    for (int i = 0; i < 4; i++) {
        float2 c0 = unpack2(acc[i][0]);
        float2 c1 = unpack2(acc[i][1]);
        *(float4*)(g_xw + ((size_t)t * 64 + mm + i) * NH + n0 + nn) =
            make_float4(c0.x, c0.y, c1.x, c1.y);
    }
}

// ---------------- Kernel: out = sigmoid(hidden) @ W_ho^T + b_ho ----------------
__global__ void __launch_bounds__(256) k_out(const float* __restrict__ hidden,
                                             const float* __restrict__ Who,
                                             const float* __restrict__ bho,
                                             float* __restrict__ outp) {
    __shared__ __align__(16) float As[16][64];
    __shared__ __align__(16) float Ws[16][64];
    const int tid = threadIdx.x;
    const int n0 = blockIdx.x * 64;
    const int m0 = blockIdx.y * 64;
    const int lm = tid >> 2;
    const int lk = (tid & 3) << 2;
    const float* arow = hidden + (size_t)(m0 + lm) * NH;
    const float* wrow = Who + (size_t)(n0 + lm) * NH;
    const int tx = tid & 15, ty = tid >> 4;
    const int mm = ty << 2, nn = tx << 2;

    unsigned long long acc[4][2];
#pragma unroll
    for (int i = 0; i < 4; i++) { acc[i][0] = 0ull; acc[i][1] = 0ull; }

    for (int kb = 0; kb < NH; kb += 16) {
        float4 av = *(const float4*)(arow + kb + lk);
        av.x = sigmoidf_(av.x); av.y = sigmoidf_(av.y);
        av.z = sigmoidf_(av.z); av.w = sigmoidf_(av.w);
        float4 wv = *(const float4*)(wrow + kb + lk);
        As[lk + 0][lm] = av.x; As[lk + 1][lm] = av.y;
        As[lk + 2][lm] = av.z; As[lk + 3][lm] = av.w;
        Ws[lk + 0][lm] = wv.x; Ws[lk + 1][lm] = wv.y;
        Ws[lk + 2][lm] = wv.z; Ws[lk + 3][lm] = wv.w;
        __syncthreads();
#pragma unroll
        for (int k = 0; k < 16; k++) {
            const float4 a  = *(const float4*)(&As[k][mm]);
            const float4 bv = *(const float4*)(&Ws[k][nn]);
            const unsigned long long b0 = pack2(bv.x, bv.y);
            const unsigned long long b1 = pack2(bv.z, bv.w);
            unsigned long long ad;
            ad = dup2(a.x); acc[0][0] = fma2(ad, b0, acc[0][0]); acc[0][1] = fma2(ad, b1, acc[0][1]);
            ad = dup2(a.y); acc[1][0] = fma2(ad, b0, acc[1][0]); acc[1][1] = fma2(ad, b1, acc[1][1]);
            ad = dup2(a.z); acc[2][0] = fma2(ad, b0, acc[2][0]); acc[2][1] = fma2(ad, b1, acc[2][1]);
            ad = dup2(a.w); acc[3][0] = fma2(ad, b0, acc[3][0]); acc[3][1] = fma2(ad, b1, acc[3][1]);
        }
        __syncthreads();
    }
    const float4 bias = *(const float4*)(bho + n0 + nn);
#pragma unroll
    for (int i = 0; i < 4; i++) {
        float2 c0 = unpack2(acc[i][0]);
        float2 c1 = unpack2(acc[i][1]);
        *(float4*)(outp + (size_t)(m0 + mm + i) * NO + n0 + nn) =
            make_float4(c0.x + bias.x, c0.y + bias.y, c1.x + bias.z, c1.y + bias.w);
    }
}

extern "C" void kernel_launch(void* const* d_in, const int* in_sizes, int n_in,
                              void* d_out, int out_size) {
    const float* x     = (const float*)d_in[0];   // [B,S,I]
    const float* h0    = (const float*)d_in[1];   // [B,1,H]
    const float* Wih   = (const float*)d_in[2];   // [H,I]
    const float* Whh   = (const float*)d_in[3];   // [H,H]
    const float* Who   = (const float*)d_in[4];   // [O,H]
    const float* bho   = (const float*)d_in[5];   // [O]
    const float* noise = (const float*)d_in[6];   // [S,B,1,H]
    float* outp = (float*)d_out;

    const size_t OUTE = (size_t)NB * NS * NO;
    const size_t HIDE = (size_t)NB * NS * NH;

    float* hidden;
    if ((size_t)out_size >= OUTE + HIDE) {
        hidden = outp + OUTE;   // harness output = concat(out, hidden)
    } else {
        void* p = nullptr;
        cudaGetSymbolAddress(&p, g_hid_fb);
        hidden = (float*)p;
    }

    // 1. input projection for all timesteps (independent of recurrence)
    k_xw<<<dim3(NH / 64, NS), 256>>>(x, Wih);

    // 2. full recurrence in ONE persistent kernel (3 graph nodes total)
    k_recur<<<GB, 256>>>(h0, Whh, noise, hidden);

    // 3. output projection
    k_out<<<dim3(NO / 64, (NB * NS) / 64), 256>>>(hidden, Who, bho, outp);
}

// round 5
// speedup vs baseline: 1.6187x; 1.6187x over previous
#include <cuda_runtime.h>
#include <cuda_bf16.h>
#include <cstdint>

// ---------------- problem constants ----------------
namespace {
constexpr int NB = 64;     // batch
constexpr int NS = 1024;   // sequence length
constexpr int NI = 512;    // input dim
constexpr int NH = 2048;   // hidden dim
constexpr int NO = 512;    // output dim
constexpr int BH = NB * NH;      // 131072 state elements

constexpr int GB = 128;          // persistent blocks (1/SM, co-resident)
constexpr int SK = 8;            // split-K chunks
constexpr int KC = NH / SK;      // 256 K per block

// smem tile pitch: 512B of K data + 16B pad -> conflict-free ldmatrix
constexpr int PITCH = 528;
constexpr int SM_W_HI = 0;                       // 128 rows
constexpr int SM_W_LO = SM_W_HI + 128 * PITCH;   // 128 rows
constexpr int SM_B_HI = SM_W_LO + 128 * PITCH;   // 64 rows
constexpr int SM_B_LO = SM_B_HI + 64 * PITCH;    // 64 rows
constexpr int SM_TOTAL = SM_B_LO + 64 * PITCH;   // 202752 B
}

// ---------------- scratch (static device allocations) ----------------
__device__ float g_xwn[(size_t)NS * NB * NH];     // [t][h][b] xw + 0.1*noise
__device__ float g_hid_fb[(size_t)NB * NS * NH];  // fallback hidden storage
__device__ float g_part[(size_t)SK * BH];         // partials [sk][h][b]
__device__ float g_h[BH];                         // hidden state [h][b]
__device__ __nv_bfloat16 g_sigh_hi[BH];           // sigmoid(h) hi [b][h]
__device__ __nv_bfloat16 g_sigh_lo[BH];           // sigmoid(h) lo [b][h]

// grid-barrier state (returns to {0,0} at end of every launch)
__device__ unsigned g_count;
__device__ unsigned g_flag;

// ---------------- helpers ----------------
__device__ __forceinline__ float sigmoidf_(float x) {
    return 1.0f / (1.0f + __expf(-x));
}
__device__ __forceinline__ unsigned bf2pack(float a, float b) {
    __nv_bfloat162 t;
    t.x = __float2bfloat16_rn(a);
    t.y = __float2bfloat16_rn(b);
    return *reinterpret_cast<unsigned*>(&t);
}
__device__ __forceinline__ uint32_t smem_u32(const void* p) {
    uint32_t a;
    asm("{ .reg .u64 t; cvta.to.shared.u64 t, %1; cvt.u32.u64 %0, t; }"
        : "=r"(a) : "l"(p));
    return a;
}
__device__ __forceinline__ void ldsm4(unsigned* r, uint32_t addr) {
    asm volatile("ldmatrix.sync.aligned.m8n8.x4.shared.b16 {%0,%1,%2,%3}, [%4];"
                 : "=r"(r[0]), "=r"(r[1]), "=r"(r[2]), "=r"(r[3]) : "r"(addr));
}
__device__ __forceinline__ void mma_bf16(float* d, const unsigned* a, const unsigned* b) {
    asm volatile(
        "mma.sync.aligned.m16n8k16.row.col.f32.bf16.bf16.f32 "
        "{%0,%1,%2,%3}, {%4,%5,%6,%7}, {%8,%9}, {%0,%1,%2,%3};"
        : "+f"(d[0]), "+f"(d[1]), "+f"(d[2]), "+f"(d[3])
        : "r"(a[0]), "r"(a[1]), "r"(a[2]), "r"(a[3]), "r"(b[0]), "r"(b[1]));
}

// ---------------- software grid barrier (sense reversal) ----------------
__device__ __forceinline__ void grid_barrier(unsigned want) {
    __syncthreads();
    if (threadIdx.x == 0) {
        unsigned* cnt = &g_count;
        unsigned* flg = &g_flag;
        unsigned old;
        asm volatile("atom.acq_rel.gpu.global.add.u32 %0, [%1], 1;"
                     : "=r"(old) : "l"(cnt) : "memory");
        if (old == (unsigned)(GB - 1)) {
            asm volatile("st.relaxed.gpu.global.u32 [%0], %1;" :: "l"(cnt), "r"(0u) : "memory");
            asm volatile("st.release.gpu.global.u32 [%0], %1;" :: "l"(flg), "r"(want) : "memory");
        } else {
            unsigned v;
            do {
                asm volatile("ld.acquire.gpu.global.u32 %0, [%1];"
                             : "=r"(v) : "l"(flg) : "memory");
            } while (v != want);
        }
    }
    __syncthreads();
}

// ---------------- persistent recurrence kernel (HMMA bf16 3-term split) ----------------
// Block (nt, sk): D[128 h-rows, 64 b] += Whh[nt*128.., kchunk] x sigh[b, kchunk]^T
// W chunk converted to bf16 hi/lo ONCE into SMEM; sigh tile restaged per step.
__global__ void __launch_bounds__(256, 1)
k_recur(const float* __restrict__ h0, const float* __restrict__ Whh,
        float* __restrict__ hidden) {
    extern __shared__ __align__(1024) char sm[];
    const uint32_t smb = smem_u32(sm);
    const int tid = threadIdx.x;
    const int wid = tid >> 5;
    const int lane = tid & 31;
    const int bx = blockIdx.x;
    const int nt = bx >> 3;            // 0..15
    const int sk = bx & 7;             // 0..7
    const int n0 = nt * 128;           // W row base
    const int kbeg = sk * KC;          // K chunk base

    // ---- one-time: stage W chunk as bf16 hi/lo into SMEM ----
    // warp handles one row per iter; lane covers 8 consecutive floats (32B gmem, 16B smem)
    for (int it = 0; it < 16; it++) {
        const int r = it * 8 + wid;                     // 0..127
        const float* wrow = Whh + (size_t)(n0 + r) * NH + kbeg + lane * 8;
        float4 v0 = *(const float4*)(wrow);
        float4 v1 = *(const float4*)(wrow + 4);
        float f[8] = {v0.x, v0.y, v0.z, v0.w, v1.x, v1.y, v1.z, v1.w};
        unsigned H[4], L[4];
#pragma unroll
        for (int j = 0; j < 4; j++) {
            float h0f = __bfloat162float(__float2bfloat16_rn(f[2 * j]));
            float h1f = __bfloat162float(__float2bfloat16_rn(f[2 * j + 1]));
            H[j] = bf2pack(f[2 * j], f[2 * j + 1]);
            L[j] = bf2pack(f[2 * j] - h0f, f[2 * j + 1] - h1f);
        }
        *(uint4*)(sm + SM_W_HI + r * PITCH + lane * 16) = make_uint4(H[0], H[1], H[2], H[3]);
        *(uint4*)(sm + SM_W_LO + r * PITCH + lane * 16) = make_uint4(L[0], L[1], L[2], L[3]);
    }

    // ---- init state: g_h[h][b], sigh[b][h] hi/lo ----
    {
        const int ui = (bx << 10) + (tid << 2);
        const int h = ui >> 6, b = ui & 63;
        float v0 = h0[(size_t)(b + 0) * NH + h];
        float v1 = h0[(size_t)(b + 1) * NH + h];
        float v2 = h0[(size_t)(b + 2) * NH + h];
        float v3 = h0[(size_t)(b + 3) * NH + h];
        *(float4*)(g_h + ui) = make_float4(v0, v1, v2, v3);
        float s[4] = {sigmoidf_(v0), sigmoidf_(v1), sigmoidf_(v2), sigmoidf_(v3)};
#pragma unroll
        for (int j = 0; j < 4; j++) {
            float hi = __bfloat162float(__float2bfloat16_rn(s[j]));
            g_sigh_hi[(size_t)(b + j) * NH + h] = __float2bfloat16_rn(s[j]);
            g_sigh_lo[(size_t)(b + j) * NH + h] = __float2bfloat16_rn(s[j] - hi);
        }
    }
    unsigned want = 1;
    grid_barrier(want); want ^= 1;   // barrier #1

    // ---- per-thread constants ----
    const int warp_m0 = (wid >> 1) * 32;       // W-row tile of this warp
    const int warp_n0 = (wid & 1) * 32;        // batch tile of this warp
    // A (W) ldmatrix address: row = m + (lane&15), col16 = (lane>>4)*16
    const uint32_t aOff = (uint32_t)((warp_m0 + (lane & 15)) * PITCH + ((lane >> 4) << 4));
    const uint32_t aHiA = smb + SM_W_HI + aOff;
    const uint32_t aLoA = smb + SM_W_LO + aOff;
    // B (sigh) ldmatrix address: row = n + (lane&7) + ((lane>>4)<<3), col16 = ((lane>>3)&1)*16
    const uint32_t bOff = (uint32_t)((warp_n0 + (lane & 7) + ((lane >> 4) << 3)) * PITCH +
                                     (((lane >> 3) & 1) << 4));
    const uint32_t bHiA = smb + SM_B_HI + bOff;
    const uint32_t bLoA = smb + SM_B_LO + bOff;

    const int ui = (bx << 10) + (tid << 2);
    const int uh = ui >> 6, ub = ui & 63;
    float* hb = hidden + (size_t)ub * NS * NH + uh;
    // epilogue store base: g_part[sk][h][b]
    float* partbase = g_part + (size_t)sk * BH;

    for (int t = 0; t < NS; t++) {
        // ---- stage sigh tile (bf16 hi/lo) into SMEM, one row per warp per iter ----
#pragma unroll
        for (int it = 0; it < 8; it++) {
            const int r = it * 8 + wid;   // batch row 0..63
            uint4 hv = *(const uint4*)(g_sigh_hi + (size_t)r * NH + kbeg + lane * 8);
            uint4 lv = *(const uint4*)(g_sigh_lo + (size_t)r * NH + kbeg + lane * 8);
            *(uint4*)(sm + SM_B_HI + r * PITCH + lane * 16) = hv;
            *(uint4*)(sm + SM_B_LO + r * PITCH + lane * 16) = lv;
        }
        __syncthreads();

        // ---- GEMM: 16 k-steps x (8 ldmatrix + 24 HMMA) ----
        float acc[2][4][4];
#pragma unroll
        for (int mi = 0; mi < 2; mi++)
#pragma unroll
            for (int ni = 0; ni < 4; ni++)
#pragma unroll
                for (int j = 0; j < 4; j++) acc[mi][ni][j] = 0.0f;

#pragma unroll 4
        for (int ks = 0; ks < 16; ks++) {
            const uint32_t ko = ks * 32;
            unsigned ahi[2][4], alo[2][4], bhi[4][2], blo[4][2];
            ldsm4(ahi[0], aHiA + ko);
            ldsm4(ahi[1], aHiA + ko + 16 * PITCH);
            ldsm4(alo[0], aLoA + ko);
            ldsm4(alo[1], aLoA + ko + 16 * PITCH);
            ldsm4(&bhi[0][0], bHiA + ko);
            ldsm4(&bhi[2][0], bHiA + ko + 16 * PITCH);
            ldsm4(&blo[0][0], bLoA + ko);
            ldsm4(&blo[2][0], bLoA + ko + 16 * PITCH);
#pragma unroll
            for (int mi = 0; mi < 2; mi++) {
#pragma unroll
                for (int ni = 0; ni < 4; ni++) {
                    mma_bf16(acc[mi][ni], ahi[mi], bhi[ni]);
                    mma_bf16(acc[mi][ni], ahi[mi], blo[ni]);
                    mma_bf16(acc[mi][ni], alo[mi], bhi[ni]);
                }
            }
        }
        __syncthreads();   // smem reads done before next-step restage

        // ---- epilogue: write partials g_part[sk][h][b] ----
        {
            const int rq = lane >> 2;            // 0..7
            const int cq = (lane & 3) * 2;       // 0,2,4,6
#pragma unroll
            for (int mi = 0; mi < 2; mi++) {
                const int hrow = n0 + warp_m0 + mi * 16 + rq;
#pragma unroll
                for (int ni = 0; ni < 4; ni++) {
                    const int bcol = warp_n0 + ni * 8 + cq;
                    float* p0 = partbase + (size_t)hrow * 64 + bcol;
                    p0[0] = acc[mi][ni][0];
                    p0[1] = acc[mi][ni][1];
                    float* p1 = p0 + 8 * 64;
                    p1[0] = acc[mi][ni][2];
                    p1[1] = acc[mi][ni][3];
                }
            }
        }
        grid_barrier(want); want ^= 1;

        // ---- fused Euler update ----
        {
            float4 s0 = *(const float4*)(g_part + ui);
            float4 s1 = *(const float4*)(g_part + (size_t)BH + ui);
            float4 s2 = *(const float4*)(g_part + (size_t)2 * BH + ui);
            float4 s3 = *(const float4*)(g_part + (size_t)3 * BH + ui);
            float4 s4 = *(const float4*)(g_part + (size_t)4 * BH + ui);
            float4 s5 = *(const float4*)(g_part + (size_t)5 * BH + ui);
            float4 s6 = *(const float4*)(g_part + (size_t)6 * BH + ui);
            float4 s7 = *(const float4*)(g_part + (size_t)7 * BH + ui);
            float4 xw = *(const float4*)(g_xwn + (size_t)t * BH + ui);
            float4 hp = *(const float4*)(g_h + ui);
            float4 v;
            v.x = 0.9f * hp.x + 0.1f * (s0.x + s1.x + s2.x + s3.x + s4.x + s5.x + s6.x + s7.x + xw.x);
            v.y = 0.9f * hp.y + 0.1f * (s0.y + s1.y + s2.y + s3.y + s4.y + s5.y + s6.y + s7.y + xw.y);
            v.z = 0.9f * hp.z + 0.1f * (s0.z + s1.z + s2.z + s3.z + s4.z + s5.z + s6.z + s7.z + xw.z);
            v.w = 0.9f * hp.w + 0.1f * (s0.w + s1.w + s2.w + s3.w + s4.w + s5.w + s6.w + s7.w + xw.w);
            *(float4*)(g_h + ui) = v;
            float vv[4] = {v.x, v.y, v.z, v.w};
#pragma unroll
            for (int j = 0; j < 4; j++) {
                hb[(size_t)j * NS * NH + (size_t)t * NH] = vv[j];
                float s = sigmoidf_(vv[j]);
                float hi = __bfloat162float(__float2bfloat16_rn(s));
                g_sigh_hi[(size_t)(ub + j) * NH + uh] = __float2bfloat16_rn(s);
                g_sigh_lo[(size_t)(ub + j) * NH + uh] = __float2bfloat16_rn(s - hi);
            }
        }
        grid_barrier(want); want ^= 1;
    }

    // padding barrier -> total 2050 (even): g_flag/g_count end at 0
    grid_barrier(want);
}

// ---------------- f32x2 helpers for the SIMT projection kernels ----------------
__device__ __forceinline__ unsigned long long pack2(float x, float y) {
    unsigned long long r;
    asm("mov.b64 %0, {%1,%2};" : "=l"(r) : "r"(__float_as_uint(x)), "r"(__float_as_uint(y)));
    return r;
}
__device__ __forceinline__ unsigned long long dup2(float x) {
    unsigned long long r;
    unsigned u = __float_as_uint(x);
    asm("mov.b64 %0, {%1,%2};" : "=l"(r) : "r"(u), "r"(u));
    return r;
}
__device__ __forceinline__ unsigned long long fma2(unsigned long long a,
                                                   unsigned long long b,
                                                   unsigned long long c) {
    unsigned long long d;
    asm("fma.rn.f32x2 %0, %1, %2, %3;" : "=l"(d) : "l"(a), "l"(b), "l"(c));
    return d;
}
__device__ __forceinline__ float2 unpack2(unsigned long long v) {
    unsigned lo, hi;
    asm("mov.b64 {%0,%1}, %2;" : "=r"(lo), "=r"(hi) : "l"(v));
    return make_float2(__uint_as_float(lo), __uint_as_float(hi));
}

// ---------------- k_xw: xwn[t][h][b] = x[b][t]@W_ih^T + 0.1*noise[t][b][h] ----------------
__global__ void __launch_bounds__(256) k_xw(const float* __restrict__ x,
                                            const float* __restrict__ Wih,
                                            const float* __restrict__ noise) {
    __shared__ __align__(16) float As[16][64];
    __shared__ __align__(16) float Ws[16][64];
    __shared__ float tr[64 * 65];
    const int tid = threadIdx.x;
    const int n0 = blockIdx.x * 64;   // h tile
    const int t  = blockIdx.y;
    const int lm = tid >> 2;
    const int lk = (tid & 3) << 2;
    const float* arow = x + ((size_t)lm * NS + t) * NI;   // row = batch lm
    const float* wrow = Wih + (size_t)(n0 + lm) * NI;
    const int tx = tid & 15, ty = tid >> 4;
    const int mm = ty << 2, nn = tx << 2;

    unsigned long long acc[4][2];
#pragma unroll
    for (int i = 0; i < 4; i++) { acc[i][0] = 0ull; acc[i][1] = 0ull; }

    for (int kb = 0; kb < NI; kb += 16) {
        float4 av = *(const float4*)(arow + kb + lk);
        float4 wv = *(const float4*)(wrow + kb + lk);
        As[lk + 0][lm] = av.x; As[lk + 1][lm] = av.y;
        As[lk + 2][lm] = av.z; As[lk + 3][lm] = av.w;
        Ws[lk + 0][lm] = wv.x; Ws[lk + 1][lm] = wv.y;
        Ws[lk + 2][lm] = wv.z; Ws[lk + 3][lm] = wv.w;
        __syncthreads();
#pragma unroll
        for (int k = 0; k < 16; k++) {
            const float4 a  = *(const float4*)(&As[k][mm]);
            const float4 bv = *(const float4*)(&Ws[k][nn]);
            const unsigned long long b0 = pack2(bv.x, bv.y);
            const unsigned long long b1 = pack2(bv.z, bv.w);
            unsigned long long ad;
            ad = dup2(a.x); acc[0][0] = fma2(ad, b0, acc[0][0]); acc[0][1] = fma2(ad, b1, acc[0][1]);
            ad = dup2(a.y); acc[1][0] = fma2(ad, b0, acc[1][0]); acc[1][1] = fma2(ad, b1, acc[1][1]);
            ad = dup2(a.z); acc[2][0] = fma2(ad, b0, acc[2][0]); acc[2][1] = fma2(ad, b1, acc[2][1]);
            ad = dup2(a.w); acc[3][0] = fma2(ad, b0, acc[3][0]); acc[3][1] = fma2(ad, b1, acc[3][1]);
        }
        __syncthreads();
    }
    // add 0.1*noise (coalesced read), stage to smem for transpose
#pragma unroll
    for (int i = 0; i < 4; i++) {
        float2 c0 = unpack2(acc[i][0]);
        float2 c1 = unpack2(acc[i][1]);
        const int b = mm + i;
        float4 nv = *(const float4*)(noise + (size_t)t * BH + (size_t)b * NH + n0 + nn);
        tr[b * 65 + nn + 0] = c0.x + 0.1f * nv.x;
        tr[b * 65 + nn + 1] = c0.y + 0.1f * nv.y;
        tr[b * 65 + nn + 2] = c1.x + 0.1f * nv.z;
        tr[b * 65 + nn + 3] = c1.y + 0.1f * nv.w;
    }
    __syncthreads();
    // transposed coalesced store: xwn[t][h][b]
#pragma unroll
    for (int i = 0; i < 4; i++) {
        const int hl = ty * 4 + i;
        float4 o;
        o.x = tr[(tx * 4 + 0) * 65 + hl];
        o.y = tr[(tx * 4 + 1) * 65 + hl];
        o.z = tr[(tx * 4 + 2) * 65 + hl];
        o.w = tr[(tx * 4 + 3) * 65 + hl];
        *(float4*)(g_xwn + (size_t)t * BH + (size_t)(n0 + hl) * 64 + tx * 4) = o;
    }
}

// ---------------- k_out: out = sigmoid(hidden) @ W_ho^T + b_ho ----------------
__global__ void __launch_bounds__(256) k_out(const float* __restrict__ hidden,
                                             const float* __restrict__ Who,
                                             const float* __restrict__ bho,
                                             float* __restrict__ outp) {
    __shared__ __align__(16) float As[16][64];
    __shared__ __align__(16) float Ws[16][64];
    const int tid = threadIdx.x;
    const int n0 = blockIdx.x * 64;
    const int m0 = blockIdx.y * 64;
    const int lm = tid >> 2;
    const int lk = (tid & 3) << 2;
    const float* arow = hidden + (size_t)(m0 + lm) * NH;
    const float* wrow = Who + (size_t)(n0 + lm) * NH;
    const int tx = tid & 15, ty = tid >> 4;
    const int mm = ty << 2, nn = tx << 2;

    unsigned long long acc[4][2];
#pragma unroll
    for (int i = 0; i < 4; i++) { acc[i][0] = 0ull; acc[i][1] = 0ull; }

    for (int kb = 0; kb < NH; kb += 16) {
        float4 av = *(const float4*)(arow + kb + lk);
        av.x = sigmoidf_(av.x); av.y = sigmoidf_(av.y);
        av.z = sigmoidf_(av.z); av.w = sigmoidf_(av.w);
        float4 wv = *(const float4*)(wrow + kb + lk);
        As[lk + 0][lm] = av.x; As[lk + 1][lm] = av.y;
        As[lk + 2][lm] = av.z; As[lk + 3][lm] = av.w;
        Ws[lk + 0][lm] = wv.x; Ws[lk + 1][lm] = wv.y;
        Ws[lk + 2][lm] = wv.z; Ws[lk + 3][lm] = wv.w;
        __syncthreads();
#pragma unroll
        for (int k = 0; k < 16; k++) {
            const float4 a  = *(const float4*)(&As[k][mm]);
            const float4 bv = *(const float4*)(&Ws[k][nn]);
            const unsigned long long b0 = pack2(bv.x, bv.y);
            const unsigned long long b1 = pack2(bv.z, bv.w);
            unsigned long long ad;
            ad = dup2(a.x); acc[0][0] = fma2(ad, b0, acc[0][0]); acc[0][1] = fma2(ad, b1, acc[0][1]);
            ad = dup2(a.y); acc[1][0] = fma2(ad, b0, acc[1][0]); acc[1][1] = fma2(ad, b1, acc[1][1]);
            ad = dup2(a.z); acc[2][0] = fma2(ad, b0, acc[2][0]); acc[2][1] = fma2(ad, b1, acc[2][1]);
            ad = dup2(a.w); acc[3][0] = fma2(ad, b0, acc[3][0]); acc[3][1] = fma2(ad, b1, acc[3][1]);
        }
        __syncthreads();
    }
    const float4 bias = *(const float4*)(bho + n0 + nn);
#pragma unroll
    for (int i = 0; i < 4; i++) {
        float2 c0 = unpack2(acc[i][0]);
        float2 c1 = unpack2(acc[i][1]);
        *(float4*)(outp + (size_t)(m0 + mm + i) * NO + n0 + nn) =
            make_float4(c0.x + bias.x, c0.y + bias.y, c1.x + bias.z, c1.y + bias.w);
    }
}

extern "C" void kernel_launch(void* const* d_in, const int* in_sizes, int n_in,
                              void* d_out, int out_size) {
    const float* x     = (const float*)d_in[0];   // [B,S,I]
    const float* h0    = (const float*)d_in[1];   // [B,1,H]
    const float* Wih   = (const float*)d_in[2];   // [H,I]
    const float* Whh   = (const float*)d_in[3];   // [H,H]
    const float* Who   = (const float*)d_in[4];   // [O,H]
    const float* bho   = (const float*)d_in[5];   // [O]
    const float* noise = (const float*)d_in[6];   // [S,B,1,H]
    float* outp = (float*)d_out;

    const size_t OUTE = (size_t)NB * NS * NO;
    const size_t HIDE = (size_t)NB * NS * NH;

    float* hidden;
    if ((size_t)out_size >= OUTE + HIDE) {
        hidden = outp + OUTE;   // harness output = concat(out, hidden)
    } else {
        void* p = nullptr;
        cudaGetSymbolAddress(&p, g_hid_fb);
        hidden = (float*)p;
    }

    cudaFuncSetAttribute(k_recur, cudaFuncAttributeMaxDynamicSharedMemorySize, SM_TOTAL);

    // 1. input projection (+noise fold, transposed to [t][h][b])
    k_xw<<<dim3(NH / 64, NS), 256>>>(x, Wih, noise);

    // 2. full recurrence: persistent HMMA kernel (3 graph nodes total)
    k_recur<<<GB, 256, SM_TOTAL>>>(h0, Whh, hidden);

    // 3. output projection
    k_out<<<dim3(NO / 64, (NB * NS) / 64), 256>>>(hidden, Who, bho, outp);
}

// round 6
// speedup vs baseline: 1.8444x; 1.1394x over previous
#include <cuda_runtime.h>
#include <cuda_fp16.h>
#include <cstdint>

// ---------------- problem constants ----------------
namespace {
constexpr int NB = 64;     // batch
constexpr int NS = 1024;   // sequence length
constexpr int NI = 512;    // input dim
constexpr int NH = 2048;   // hidden dim
constexpr int NO = 512;    // output dim
constexpr int BH = NB * NH;      // 131072 state elements

constexpr int GB = 128;          // persistent blocks (1/SM, co-resident)
constexpr int SK = 8;            // split-K chunks
constexpr int KC = NH / SK;      // 256 K per block

// smem tile pitch: 512B of K data + 16B pad -> conflict-free ldmatrix
constexpr int PITCH = 528;
constexpr int SM_W_HI = 0;                       // 128 rows (fp16 hi)
constexpr int SM_W_LO = SM_W_HI + 128 * PITCH;   // 128 rows (fp16 lo)
constexpr int SM_B    = SM_W_LO + 128 * PITCH;   // 64 rows  (fp16 sigh)
constexpr int SM_TOTAL = SM_B + 64 * PITCH;      // 168960 B
}

// ---------------- scratch (static device allocations) ----------------
__device__ float g_xwn[(size_t)NS * NB * NH];     // [t][h][b] xw + 0.1*noise
__device__ float g_hid_fb[(size_t)NB * NS * NH];  // fallback hidden storage
__device__ float g_part[(size_t)SK * BH];         // partials [sk][h][b]
__device__ float g_h[BH];                         // hidden state [h][b]
__device__ __half g_sigh[BH];                     // sigmoid(h) fp16 [b][h]

// grid-barrier state (returns to {0,0} at end of every launch)
__device__ unsigned g_count;
__device__ unsigned g_flag;

// ---------------- helpers ----------------
__device__ __forceinline__ float sigmoidf_(float x) {
    return 1.0f / (1.0f + __expf(-x));
}
__device__ __forceinline__ unsigned h2pack(float a, float b) {
    __half2 t;
    t.x = __float2half_rn(a);
    t.y = __float2half_rn(b);
    return *reinterpret_cast<unsigned*>(&t);
}
__device__ __forceinline__ uint32_t smem_u32(const void* p) {
    uint32_t a;
    asm("{ .reg .u64 t; cvta.to.shared.u64 t, %1; cvt.u32.u64 %0, t; }"
        : "=r"(a) : "l"(p));
    return a;
}
__device__ __forceinline__ void ldsm4(unsigned* r, uint32_t addr) {
    asm volatile("ldmatrix.sync.aligned.m8n8.x4.shared.b16 {%0,%1,%2,%3}, [%4];"
                 : "=r"(r[0]), "=r"(r[1]), "=r"(r[2]), "=r"(r[3]) : "r"(addr));
}
__device__ __forceinline__ void mma_f16(float* d, const unsigned* a, const unsigned* b) {
    asm volatile(
        "mma.sync.aligned.m16n8k16.row.col.f32.f16.f16.f32 "
        "{%0,%1,%2,%3}, {%4,%5,%6,%7}, {%8,%9}, {%0,%1,%2,%3};"
        : "+f"(d[0]), "+f"(d[1]), "+f"(d[2]), "+f"(d[3])
        : "r"(a[0]), "r"(a[1]), "r"(a[2]), "r"(a[3]), "r"(b[0]), "r"(b[1]));
}

// ---------------- software grid barrier (sense reversal) ----------------
__device__ __forceinline__ void grid_barrier(unsigned want) {
    __syncthreads();
    if (threadIdx.x == 0) {
        unsigned* cnt = &g_count;
        unsigned* flg = &g_flag;
        unsigned old;
        asm volatile("atom.acq_rel.gpu.global.add.u32 %0, [%1], 1;"
                     : "=r"(old) : "l"(cnt) : "memory");
        if (old == (unsigned)(GB - 1)) {
            asm volatile("st.relaxed.gpu.global.u32 [%0], %1;" :: "l"(cnt), "r"(0u) : "memory");
            asm volatile("st.release.gpu.global.u32 [%0], %1;" :: "l"(flg), "r"(want) : "memory");
        } else {
            unsigned v;
            do {
                asm volatile("ld.acquire.gpu.global.u32 %0, [%1];"
                             : "=r"(v) : "l"(flg) : "memory");
            } while (v != want);
        }
    }
    __syncthreads();
}

// ---------------- persistent recurrence kernel (HMMA fp16 2-term W-split) ----------------
// Block (nt, sk): D[128 h-rows, 64 b] = (Whi+Wlo)[nt*128.., kchunk] x sigh_f16[b, kchunk]^T
// W chunk converted to fp16 hi/lo ONCE into SMEM; sigh tile restaged per step.
__global__ void __launch_bounds__(256, 1)
k_recur(const float* __restrict__ h0, const float* __restrict__ Whh,
        float* __restrict__ hidden) {
    extern __shared__ __align__(1024) char sm[];
    const uint32_t smb = smem_u32(sm);
    const int tid = threadIdx.x;
    const int wid = tid >> 5;
    const int lane = tid & 31;
    const int bx = blockIdx.x;
    const int nt = bx >> 3;            // 0..15
    const int sk = bx & 7;             // 0..7
    const int n0 = nt * 128;           // W row base
    const int kbeg = sk * KC;          // K chunk base

    // ---- one-time: stage W chunk as fp16 hi/lo into SMEM ----
    for (int it = 0; it < 16; it++) {
        const int r = it * 8 + wid;                     // 0..127
        const float* wrow = Whh + (size_t)(n0 + r) * NH + kbeg + lane * 8;
        float4 v0 = *(const float4*)(wrow);
        float4 v1 = *(const float4*)(wrow + 4);
        float f[8] = {v0.x, v0.y, v0.z, v0.w, v1.x, v1.y, v1.z, v1.w};
        unsigned H[4], L[4];
#pragma unroll
        for (int j = 0; j < 4; j++) {
            float h0f = __half2float(__float2half_rn(f[2 * j]));
            float h1f = __half2float(__float2half_rn(f[2 * j + 1]));
            H[j] = h2pack(f[2 * j], f[2 * j + 1]);
            L[j] = h2pack(f[2 * j] - h0f, f[2 * j + 1] - h1f);
        }
        *(uint4*)(sm + SM_W_HI + r * PITCH + lane * 16) = make_uint4(H[0], H[1], H[2], H[3]);
        *(uint4*)(sm + SM_W_LO + r * PITCH + lane * 16) = make_uint4(L[0], L[1], L[2], L[3]);
    }

    // ---- init state: g_h[h][b], sigh fp16 [b][h] ----
    {
        const int ui = (bx << 10) + (tid << 2);
        const int h = ui >> 6, b = ui & 63;
        float v0 = h0[(size_t)(b + 0) * NH + h];
        float v1 = h0[(size_t)(b + 1) * NH + h];
        float v2 = h0[(size_t)(b + 2) * NH + h];
        float v3 = h0[(size_t)(b + 3) * NH + h];
        *(float4*)(g_h + ui) = make_float4(v0, v1, v2, v3);
        g_sigh[(size_t)(b + 0) * NH + h] = __float2half_rn(sigmoidf_(v0));
        g_sigh[(size_t)(b + 1) * NH + h] = __float2half_rn(sigmoidf_(v1));
        g_sigh[(size_t)(b + 2) * NH + h] = __float2half_rn(sigmoidf_(v2));
        g_sigh[(size_t)(b + 3) * NH + h] = __float2half_rn(sigmoidf_(v3));
    }
    unsigned want = 1;
    grid_barrier(want); want ^= 1;   // barrier #1

    // ---- per-thread constants ----
    const int warp_m0 = (wid >> 1) * 32;       // W-row tile of this warp
    const int warp_n0 = (wid & 1) * 32;        // batch tile of this warp
    const uint32_t aOff = (uint32_t)((warp_m0 + (lane & 15)) * PITCH + ((lane >> 4) << 4));
    const uint32_t aHiA = smb + SM_W_HI + aOff;
    const uint32_t aLoA = smb + SM_W_LO + aOff;
    const uint32_t bOff = (uint32_t)((warp_n0 + (lane & 7) + ((lane >> 4) << 3)) * PITCH +
                                     (((lane >> 3) & 1) << 4));
    const uint32_t bA = smb + SM_B + bOff;

    const int ui = (bx << 10) + (tid << 2);
    const int uh = ui >> 6, ub = ui & 63;
    float* hb = hidden + (size_t)ub * NS * NH + uh;
    float* partbase = g_part + (size_t)sk * BH;

    for (int t = 0; t < NS; t++) {
        // ---- prefetch update-phase operands (hide DRAM/L2 latency behind GEMM) ----
        const float4 xw = __ldcs((const float4*)(g_xwn + (size_t)t * BH + ui));
        const float4 hp = *(const float4*)(g_h + ui);

        // ---- stage sigh tile (fp16) into SMEM, one row per warp per iter ----
#pragma unroll
        for (int it = 0; it < 8; it++) {
            const int r = it * 8 + wid;   // batch row 0..63
            uint4 hv = *(const uint4*)(g_sigh + (size_t)r * NH + kbeg + lane * 8);
            *(uint4*)(sm + SM_B + r * PITCH + lane * 16) = hv;
        }
        __syncthreads();

        // ---- GEMM: 16 k-steps x (6 ldmatrix + 16 HMMA) ----
        float acc[2][4][4];
#pragma unroll
        for (int mi = 0; mi < 2; mi++)
#pragma unroll
            for (int ni = 0; ni < 4; ni++)
#pragma unroll
                for (int j = 0; j < 4; j++) acc[mi][ni][j] = 0.0f;

#pragma unroll 4
        for (int ks = 0; ks < 16; ks++) {
            const uint32_t ko = ks * 32;
            unsigned whi[2][4], wlo[2][4], bm[4][2];
            ldsm4(whi[0], aHiA + ko);
            ldsm4(whi[1], aHiA + ko + 16 * PITCH);
            ldsm4(wlo[0], aLoA + ko);
            ldsm4(wlo[1], aLoA + ko + 16 * PITCH);
            ldsm4(&bm[0][0], bA + ko);
            ldsm4(&bm[2][0], bA + ko + 16 * PITCH);
#pragma unroll
            for (int mi = 0; mi < 2; mi++) {
#pragma unroll
                for (int ni = 0; ni < 4; ni++) {
                    mma_f16(acc[mi][ni], whi[mi], bm[ni]);
                    mma_f16(acc[mi][ni], wlo[mi], bm[ni]);
                }
            }
        }
        __syncthreads();   // smem reads done before next-step restage

        // ---- epilogue: write partials g_part[sk][h][b] ----
        {
            const int rq = lane >> 2;            // 0..7
            const int cq = (lane & 3) * 2;       // 0,2,4,6
#pragma unroll
            for (int mi = 0; mi < 2; mi++) {
                const int hrow = n0 + warp_m0 + mi * 16 + rq;
#pragma unroll
                for (int ni = 0; ni < 4; ni++) {
                    const int bcol = warp_n0 + ni * 8 + cq;
                    float* p0 = partbase + (size_t)hrow * 64 + bcol;
                    p0[0] = acc[mi][ni][0];
                    p0[1] = acc[mi][ni][1];
                    float* p1 = p0 + 8 * 64;
                    p1[0] = acc[mi][ni][2];
                    p1[1] = acc[mi][ni][3];
                }
            }
        }
        grid_barrier(want); want ^= 1;

        // ---- fused Euler update ----
        {
            float4 s0 = *(const float4*)(g_part + ui);
            float4 s1 = *(const float4*)(g_part + (size_t)BH + ui);
            float4 s2 = *(const float4*)(g_part + (size_t)2 * BH + ui);
            float4 s3 = *(const float4*)(g_part + (size_t)3 * BH + ui);
            float4 s4 = *(const float4*)(g_part + (size_t)4 * BH + ui);
            float4 s5 = *(const float4*)(g_part + (size_t)5 * BH + ui);
            float4 s6 = *(const float4*)(g_part + (size_t)6 * BH + ui);
            float4 s7 = *(const float4*)(g_part + (size_t)7 * BH + ui);
            float4 v;
            v.x = 0.9f * hp.x + 0.1f * (s0.x + s1.x + s2.x + s3.x + s4.x + s5.x + s6.x + s7.x + xw.x);
            v.y = 0.9f * hp.y + 0.1f * (s0.y + s1.y + s2.y + s3.y + s4.y + s5.y + s6.y + s7.y + xw.y);
            v.z = 0.9f * hp.z + 0.1f * (s0.z + s1.z + s2.z + s3.z + s4.z + s5.z + s6.z + s7.z + xw.z);
            v.w = 0.9f * hp.w + 0.1f * (s0.w + s1.w + s2.w + s3.w + s4.w + s5.w + s6.w + s7.w + xw.w);
            *(float4*)(g_h + ui) = v;
            float vv[4] = {v.x, v.y, v.z, v.w};
#pragma unroll
            for (int j = 0; j < 4; j++) {
                __stcs(hb + (size_t)j * NS * NH + (size_t)t * NH, vv[j]);
                g_sigh[(size_t)(ub + j) * NH + uh] = __float2half_rn(sigmoidf_(vv[j]));
            }
        }
        grid_barrier(want); want ^= 1;
    }

    // padding barrier -> total 2050 (even): g_flag/g_count end at 0
    grid_barrier(want);
}

// ---------------- f32x2 helpers for the SIMT projection kernels ----------------
__device__ __forceinline__ unsigned long long pack2(float x, float y) {
    unsigned long long r;
    asm("mov.b64 %0, {%1,%2};" : "=l"(r) : "r"(__float_as_uint(x)), "r"(__float_as_uint(y)));
    return r;
}
__device__ __forceinline__ unsigned long long dup2(float x) {
    unsigned long long r;
    unsigned u = __float_as_uint(x);
    asm("mov.b64 %0, {%1,%2};" : "=l"(r) : "r"(u), "r"(u));
    return r;
}
__device__ __forceinline__ unsigned long long fma2(unsigned long long a,
                                                   unsigned long long b,
                                                   unsigned long long c) {
    unsigned long long d;
    asm("fma.rn.f32x2 %0, %1, %2, %3;" : "=l"(d) : "l"(a), "l"(b), "l"(c));
    return d;
}
__device__ __forceinline__ float2 unpack2(unsigned long long v) {
    unsigned lo, hi;
    asm("mov.b64 {%0,%1}, %2;" : "=r"(lo), "=r"(hi) : "l"(v));
    return make_float2(__uint_as_float(lo), __uint_as_float(hi));
}

// ---------------- k_xw: xwn[t][h][b] = x[b][t]@W_ih^T + 0.1*noise[t][b][h] ----------------
__global__ void __launch_bounds__(256) k_xw(const float* __restrict__ x,
                                            const float* __restrict__ Wih,
                                            const float* __restrict__ noise) {
    __shared__ __align__(16) float As[16][64];
    __shared__ __align__(16) float Ws[16][64];
    __shared__ float tr[64 * 65];
    const int tid = threadIdx.x;
    const int n0 = blockIdx.x * 64;   // h tile
    const int t  = blockIdx.y;
    const int lm = tid >> 2;
    const int lk = (tid & 3) << 2;
    const float* arow = x + ((size_t)lm * NS + t) * NI;   // row = batch lm
    const float* wrow = Wih + (size_t)(n0 + lm) * NI;
    const int tx = tid & 15, ty = tid >> 4;
    const int mm = ty << 2, nn = tx << 2;

    unsigned long long acc[4][2];
#pragma unroll
    for (int i = 0; i < 4; i++) { acc[i][0] = 0ull; acc[i][1] = 0ull; }

    for (int kb = 0; kb < NI; kb += 16) {
        float4 av = *(const float4*)(arow + kb + lk);
        float4 wv = *(const float4*)(wrow + kb + lk);
        As[lk + 0][lm] = av.x; As[lk + 1][lm] = av.y;
        As[lk + 2][lm] = av.z; As[lk + 3][lm] = av.w;
        Ws[lk + 0][lm] = wv.x; Ws[lk + 1][lm] = wv.y;
        Ws[lk + 2][lm] = wv.z; Ws[lk + 3][lm] = wv.w;
        __syncthreads();
#pragma unroll
        for (int k = 0; k < 16; k++) {
            const float4 a  = *(const float4*)(&As[k][mm]);
            const float4 bv = *(const float4*)(&Ws[k][nn]);
            const unsigned long long b0 = pack2(bv.x, bv.y);
            const unsigned long long b1 = pack2(bv.z, bv.w);
            unsigned long long ad;
            ad = dup2(a.x); acc[0][0] = fma2(ad, b0, acc[0][0]); acc[0][1] = fma2(ad, b1, acc[0][1]);
            ad = dup2(a.y); acc[1][0] = fma2(ad, b0, acc[1][0]); acc[1][1] = fma2(ad, b1, acc[1][1]);
            ad = dup2(a.z); acc[2][0] = fma2(ad, b0, acc[2][0]); acc[2][1] = fma2(ad, b1, acc[2][1]);
            ad = dup2(a.w); acc[3][0] = fma2(ad, b0, acc[3][0]); acc[3][1] = fma2(ad, b1, acc[3][1]);
        }
        __syncthreads();
    }
    // add 0.1*noise (coalesced read), stage to smem for transpose
#pragma unroll
    for (int i = 0; i < 4; i++) {
        float2 c0 = unpack2(acc[i][0]);
        float2 c1 = unpack2(acc[i][1]);
        const int b = mm + i;
        float4 nv = *(const float4*)(noise + (size_t)t * BH + (size_t)b * NH + n0 + nn);
        tr[b * 65 + nn + 0] = c0.x + 0.1f * nv.x;
        tr[b * 65 + nn + 1] = c0.y + 0.1f * nv.y;
        tr[b * 65 + nn + 2] = c1.x + 0.1f * nv.z;
        tr[b * 65 + nn + 3] = c1.y + 0.1f * nv.w;
    }
    __syncthreads();
    // transposed coalesced store: xwn[t][h][b]
#pragma unroll
    for (int i = 0; i < 4; i++) {
        const int hl = ty * 4 + i;
        float4 o;
        o.x = tr[(tx * 4 + 0) * 65 + hl];
        o.y = tr[(tx * 4 + 1) * 65 + hl];
        o.z = tr[(tx * 4 + 2) * 65 + hl];
        o.w = tr[(tx * 4 + 3) * 65 + hl];
        *(float4*)(g_xwn + (size_t)t * BH + (size_t)(n0 + hl) * 64 + tx * 4) = o;
    }
}

// ---------------- k_out: out = sigmoid(hidden) @ W_ho^T + b_ho ----------------
__global__ void __launch_bounds__(256) k_out(const float* __restrict__ hidden,
                                             const float* __restrict__ Who,
                                             const float* __restrict__ bho,
                                             float* __restrict__ outp) {
    __shared__ __align__(16) float As[16][64];
    __shared__ __align__(16) float Ws[16][64];
    const int tid = threadIdx.x;
    const int n0 = blockIdx.x * 64;
    const int m0 = blockIdx.y * 64;
    const int lm = tid >> 2;
    const int lk = (tid & 3) << 2;
    const float* arow = hidden + (size_t)(m0 + lm) * NH;
    const float* wrow = Who + (size_t)(n0 + lm) * NH;
    const int tx = tid & 15, ty = tid >> 4;
    const int mm = ty << 2, nn = tx << 2;

    unsigned long long acc[4][2];
#pragma unroll
    for (int i = 0; i < 4; i++) { acc[i][0] = 0ull; acc[i][1] = 0ull; }

    for (int kb = 0; kb < NH; kb += 16) {
        float4 av = *(const float4*)(arow + kb + lk);
        av.x = sigmoidf_(av.x); av.y = sigmoidf_(av.y);
        av.z = sigmoidf_(av.z); av.w = sigmoidf_(av.w);
        float4 wv = *(const float4*)(wrow + kb + lk);
        As[lk + 0][lm] = av.x; As[lk + 1][lm] = av.y;
        As[lk + 2][lm] = av.z; As[lk + 3][lm] = av.w;
        Ws[lk + 0][lm] = wv.x; Ws[lk + 1][lm] = wv.y;
        Ws[lk + 2][lm] = wv.z; Ws[lk + 3][lm] = wv.w;
        __syncthreads();
#pragma unroll
        for (int k = 0; k < 16; k++) {
            const float4 a  = *(const float4*)(&As[k][mm]);
            const float4 bv = *(const float4*)(&Ws[k][nn]);
            const unsigned long long b0 = pack2(bv.x, bv.y);
            const unsigned long long b1 = pack2(bv.z, bv.w);
            unsigned long long ad;
            ad = dup2(a.x); acc[0][0] = fma2(ad, b0, acc[0][0]); acc[0][1] = fma2(ad, b1, acc[0][1]);
            ad = dup2(a.y); acc[1][0] = fma2(ad, b0, acc[1][0]); acc[1][1] = fma2(ad, b1, acc[1][1]);
            ad = dup2(a.z); acc[2][0] = fma2(ad, b0, acc[2][0]); acc[2][1] = fma2(ad, b1, acc[2][1]);
            ad = dup2(a.w); acc[3][0] = fma2(ad, b0, acc[3][0]); acc[3][1] = fma2(ad, b1, acc[3][1]);
        }
        __syncthreads();
    }
    const float4 bias = *(const float4*)(bho + n0 + nn);
#pragma unroll
    for (int i = 0; i < 4; i++) {
        float2 c0 = unpack2(acc[i][0]);
        float2 c1 = unpack2(acc[i][1]);
        *(float4*)(outp + (size_t)(m0 + mm + i) * NO + n0 + nn) =
            make_float4(c0.x + bias.x, c0.y + bias.y, c1.x + bias.z, c1.y + bias.w);
    }
}

extern "C" void kernel_launch(void* const* d_in, const int* in_sizes, int n_in,
                              void* d_out, int out_size) {
    const float* x     = (const float*)d_in[0];   // [B,S,I]
    const float* h0    = (const float*)d_in[1];   // [B,1,H]
    const float* Wih   = (const float*)d_in[2];   // [H,I]
    const float* Whh   = (const float*)d_in[3];   // [H,H]
    const float* Who   = (const float*)d_in[4];   // [O,H]
    const float* bho   = (const float*)d_in[5];   // [O]
    const float* noise = (const float*)d_in[6];   // [S,B,1,H]
    float* outp = (float*)d_out;

    const size_t OUTE = (size_t)NB * NS * NO;
    const size_t HIDE = (size_t)NB * NS * NH;

    float* hidden;
    if ((size_t)out_size >= OUTE + HIDE) {
        hidden = outp + OUTE;   // harness output = concat(out, hidden)
    } else {
        void* p = nullptr;
        cudaGetSymbolAddress(&p, g_hid_fb);
        hidden = (float*)p;
    }

    cudaFuncSetAttribute(k_recur, cudaFuncAttributeMaxDynamicSharedMemorySize, SM_TOTAL);

    // 1. input projection (+noise fold, transposed to [t][h][b])
    k_xw<<<dim3(NH / 64, NS), 256>>>(x, Wih, noise);

    // 2. full recurrence: persistent HMMA kernel (3 graph nodes total)
    k_recur<<<GB, 256, SM_TOTAL>>>(h0, Whh, hidden);

    // 3. output projection
    k_out<<<dim3(NO / 64, (NB * NS) / 64), 256>>>(hidden, Who, bho, outp);
}

// round 7
// speedup vs baseline: 2.3171x; 1.2563x over previous
#include <cuda_runtime.h>
#include <cuda_fp16.h>
#include <cstdint>

// ---------------- problem constants ----------------
namespace {
constexpr int NB = 64;     // batch
constexpr int NS = 1024;   // sequence length
constexpr int NI = 512;    // input dim
constexpr int NH = 2048;   // hidden dim
constexpr int NO = 512;    // output dim
constexpr int BH = NB * NH;      // 131072 state elements

constexpr int GB = 128;          // persistent blocks (1/SM, co-resident)
constexpr int SK = 8;            // split-K chunks (recurrence)
constexpr int KC = NH / SK;      // 256 K per recurrence block

// smem tile pitch: 512B of K data + 16B pad -> conflict-free ldmatrix
constexpr int PITCH = 528;

// k_recur smem layout
constexpr int R_W_HI = 0;                      // 128 rows (fp16 hi)
constexpr int R_W_LO = R_W_HI + 128 * PITCH;   // 128 rows (fp16 lo)
constexpr int R_B    = R_W_LO + 128 * PITCH;   // 64 rows  (fp16 sigh)
constexpr int R_TOTAL = R_B + 64 * PITCH;      // 168960 B

// k_xw smem layout (adds fp32 noise staging area)
constexpr int X_W_HI = 0;
constexpr int X_W_LO = X_W_HI + 128 * PITCH;
constexpr int X_B    = X_W_LO + 128 * PITCH;
constexpr int X_NS   = X_B + 64 * PITCH;       // 64 rows x 132 floats
constexpr int X_TOTAL = X_NS + 64 * PITCH;     // 202752 B

// k_out smem layout
constexpr int O_W_HI = 0;
constexpr int O_W_LO = O_W_HI + 128 * PITCH;
constexpr int O_B    = O_W_LO + 128 * PITCH;
constexpr int O_TOTAL = O_B + 64 * PITCH;      // 168960 B
}

// ---------------- scratch (static device allocations) ----------------
__device__ float g_xwn[(size_t)NS * NB * NH];     // [t][h][b] xw + 0.1*noise
__device__ float g_hid_fb[(size_t)NB * NS * NH];  // fallback hidden storage
__device__ float g_part[(size_t)SK * BH];         // partials [sk][h][b]
__device__ float g_h[BH];                         // hidden state [h][b]
__device__ __half g_sigh[BH];                     // sigmoid(h) fp16 [b][h]
__device__ __half g_wih_hi[(size_t)NH * NI];      // W_ih fp16 hi [h][i]
__device__ __half g_wih_lo[(size_t)NH * NI];      // W_ih fp16 lo
__device__ __half g_who_hi[(size_t)NO * NH];      // W_ho fp16 hi [o][h]
__device__ __half g_who_lo[(size_t)NO * NH];      // W_ho fp16 lo

// grid-barrier state (returns to {0,0} at end of every launch)
__device__ unsigned g_count;
__device__ unsigned g_flag;

// ---------------- helpers ----------------
__device__ __forceinline__ float sigmoidf_(float x) {
    return 1.0f / (1.0f + __expf(-x));
}
__device__ __forceinline__ unsigned h2pack(float a, float b) {
    __half2 t;
    t.x = __float2half_rn(a);
    t.y = __float2half_rn(b);
    return *reinterpret_cast<unsigned*>(&t);
}
__device__ __forceinline__ uint32_t smem_u32(const void* p) {
    uint32_t a;
    asm("{ .reg .u64 t; cvta.to.shared.u64 t, %1; cvt.u32.u64 %0, t; }"
        : "=r"(a) : "l"(p));
    return a;
}
// ldmatrix stays volatile (must not hoist above __syncthreads)
__device__ __forceinline__ void ldsm4(unsigned* r, uint32_t addr) {
    asm volatile("ldmatrix.sync.aligned.m8n8.x4.shared.b16 {%0,%1,%2,%3}, [%4];"
                 : "=r"(r[0]), "=r"(r[1]), "=r"(r[2]), "=r"(r[3]) : "r"(addr));
}
// MMA is NON-volatile: pure register op; lets ptxas interleave for ILP
__device__ __forceinline__ void mma_f16(float* d, const unsigned* a, const unsigned* b) {
    asm("mma.sync.aligned.m16n8k16.row.col.f32.f16.f16.f32 "
        "{%0,%1,%2,%3}, {%4,%5,%6,%7}, {%8,%9}, {%0,%1,%2,%3};"
        : "+f"(d[0]), "+f"(d[1]), "+f"(d[2]), "+f"(d[3])
        : "r"(a[0]), "r"(a[1]), "r"(a[2]), "r"(a[3]), "r"(b[0]), "r"(b[1]));
}

// Shared inner GEMM: 16 k-steps over a staged [128 x 256] A (hi/lo fp16 planes)
// and [64 x 256] B (single fp16 plane). acc += (Ahi+Alo) x B^T for this warp's
// m32 x n32 tile. Issues 8 hi-MMAs then 8 lo-MMAs per k-step (8-deep ILP
// between RAW-dependent pairs).
__device__ __forceinline__ void gemm16(float acc[2][4][4], uint32_t aHi,
                                       uint32_t aLo, uint32_t bA) {
#pragma unroll 4
    for (int ks = 0; ks < 16; ks++) {
        const uint32_t ko = ks * 32;
        unsigned whi[2][4], wlo[2][4], bm[4][2];
        ldsm4(whi[0], aHi + ko);
        ldsm4(whi[1], aHi + ko + 16 * PITCH);
        ldsm4(wlo[0], aLo + ko);
        ldsm4(wlo[1], aLo + ko + 16 * PITCH);
        ldsm4(&bm[0][0], bA + ko);
        ldsm4(&bm[2][0], bA + ko + 16 * PITCH);
#pragma unroll
        for (int mi = 0; mi < 2; mi++)
#pragma unroll
            for (int ni = 0; ni < 4; ni++)
                mma_f16(acc[mi][ni], whi[mi], bm[ni]);
#pragma unroll
        for (int mi = 0; mi < 2; mi++)
#pragma unroll
            for (int ni = 0; ni < 4; ni++)
                mma_f16(acc[mi][ni], wlo[mi], bm[ni]);
    }
}

// ---------------- software grid barrier (sense reversal) ----------------
__device__ __forceinline__ void grid_barrier(unsigned want) {
    __syncthreads();
    if (threadIdx.x == 0) {
        unsigned* cnt = &g_count;
        unsigned* flg = &g_flag;
        unsigned old;
        asm volatile("atom.acq_rel.gpu.global.add.u32 %0, [%1], 1;"
                     : "=r"(old) : "l"(cnt) : "memory");
        if (old == (unsigned)(GB - 1)) {
            asm volatile("st.relaxed.gpu.global.u32 [%0], %1;" :: "l"(cnt), "r"(0u) : "memory");
            asm volatile("st.release.gpu.global.u32 [%0], %1;" :: "l"(flg), "r"(want) : "memory");
        } else {
            unsigned v;
            do {
                asm volatile("ld.acquire.gpu.global.u32 %0, [%1];"
                             : "=r"(v) : "l"(flg) : "memory");
            } while (v != want);
        }
    }
    __syncthreads();
}

// ---------------- W_ih / W_ho fp32 -> fp16 hi/lo conversion (one-time) ----------------
__global__ void __launch_bounds__(256) k_convW(const float* __restrict__ Wih,
                                               const float* __restrict__ Who) {
    const int idx = blockIdx.x * 256 + threadIdx.x;   // 2M threads
    if (idx < NH * NI) {
        float f = Wih[idx];
        __half h = __float2half_rn(f);
        g_wih_hi[idx] = h;
        g_wih_lo[idx] = __float2half_rn(f - __half2float(h));
    } else {
        int i = idx - NH * NI;
        float f = Who[i];
        __half h = __float2half_rn(f);
        g_who_hi[i] = h;
        g_who_lo[i] = __float2half_rn(f - __half2float(h));
    }
}

// ---------------- persistent recurrence kernel ----------------
__global__ void __launch_bounds__(256, 1)
k_recur(const float* __restrict__ h0, const float* __restrict__ Whh,
        float* __restrict__ hidden) {
    extern __shared__ __align__(1024) char sm[];
    const uint32_t smb = smem_u32(sm);
    const int tid = threadIdx.x;
    const int wid = tid >> 5;
    const int lane = tid & 31;
    const int bx = blockIdx.x;
    const int nt = bx >> 3;            // 0..15
    const int sk = bx & 7;             // 0..7
    const int n0 = nt * 128;           // W row base (h)
    const int kbeg = sk * KC;          // K chunk base

    // ---- one-time: stage W_hh chunk as fp16 hi/lo into SMEM ----
    for (int it = 0; it < 16; it++) {
        const int r = it * 8 + wid;                     // 0..127
        const float* wrow = Whh + (size_t)(n0 + r) * NH + kbeg + lane * 8;
        float4 v0 = *(const float4*)(wrow);
        float4 v1 = *(const float4*)(wrow + 4);
        float f[8] = {v0.x, v0.y, v0.z, v0.w, v1.x, v1.y, v1.z, v1.w};
        unsigned H[4], L[4];
#pragma unroll
        for (int j = 0; j < 4; j++) {
            float h0f = __half2float(__float2half_rn(f[2 * j]));
            float h1f = __half2float(__float2half_rn(f[2 * j + 1]));
            H[j] = h2pack(f[2 * j], f[2 * j + 1]);
            L[j] = h2pack(f[2 * j] - h0f, f[2 * j + 1] - h1f);
        }
        *(uint4*)(sm + R_W_HI + r * PITCH + lane * 16) = make_uint4(H[0], H[1], H[2], H[3]);
        *(uint4*)(sm + R_W_LO + r * PITCH + lane * 16) = make_uint4(L[0], L[1], L[2], L[3]);
    }

    // ---- init state: g_h[h][b], sigh fp16 [b][h] ----
    {
        const int ui = (bx << 10) + (tid << 2);
        const int h = ui >> 6, b = ui & 63;
        float v0 = h0[(size_t)(b + 0) * NH + h];
        float v1 = h0[(size_t)(b + 1) * NH + h];
        float v2 = h0[(size_t)(b + 2) * NH + h];
        float v3 = h0[(size_t)(b + 3) * NH + h];
        *(float4*)(g_h + ui) = make_float4(v0, v1, v2, v3);
        g_sigh[(size_t)(b + 0) * NH + h] = __float2half_rn(sigmoidf_(v0));
        g_sigh[(size_t)(b + 1) * NH + h] = __float2half_rn(sigmoidf_(v1));
        g_sigh[(size_t)(b + 2) * NH + h] = __float2half_rn(sigmoidf_(v2));
        g_sigh[(size_t)(b + 3) * NH + h] = __float2half_rn(sigmoidf_(v3));
    }
    unsigned want = 1;
    grid_barrier(want); want ^= 1;   // barrier #1

    // ---- per-thread constants ----
    const int warp_m0 = (wid >> 1) * 32;       // W-row tile of this warp
    const int warp_n0 = (wid & 1) * 32;        // batch tile of this warp
    const uint32_t aOff = (uint32_t)((warp_m0 + (lane & 15)) * PITCH + ((lane >> 4) << 4));
    const uint32_t aHiA = smb + R_W_HI + aOff;
    const uint32_t aLoA = smb + R_W_LO + aOff;
    const uint32_t bOff = (uint32_t)((warp_n0 + (lane & 7) + ((lane >> 4) << 3)) * PITCH +
                                     (((lane >> 3) & 1) << 4));
    const uint32_t bA = smb + R_B + bOff;

    const int ui = (bx << 10) + (tid << 2);
    const int uh = ui >> 6, ub = ui & 63;
    float* hb = hidden + (size_t)ub * NS * NH + uh;
    float* partbase = g_part + (size_t)sk * BH;

    for (int t = 0; t < NS; t++) {
        // prefetch update-phase operands (hide DRAM/L2 latency behind GEMM)
        const float4 xw = __ldcs((const float4*)(g_xwn + (size_t)t * BH + ui));
        const float4 hp = *(const float4*)(g_h + ui);

        // stage sigh tile (fp16) into SMEM
#pragma unroll
        for (int it = 0; it < 8; it++) {
            const int r = it * 8 + wid;   // batch row 0..63
            uint4 hv = *(const uint4*)(g_sigh + (size_t)r * NH + kbeg + lane * 8);
            *(uint4*)(sm + R_B + r * PITCH + lane * 16) = hv;
        }
        __syncthreads();

        float acc[2][4][4];
#pragma unroll
        for (int mi = 0; mi < 2; mi++)
#pragma unroll
            for (int ni = 0; ni < 4; ni++)
#pragma unroll
                for (int j = 0; j < 4; j++) acc[mi][ni][j] = 0.0f;

        gemm16(acc, aHiA, aLoA, bA);
        __syncthreads();   // smem reads done before next-step restage

        // epilogue: write partials g_part[sk][h][b]
        {
            const int rq = lane >> 2;            // 0..7
            const int cq = (lane & 3) * 2;       // 0,2,4,6
#pragma unroll
            for (int mi = 0; mi < 2; mi++) {
                const int hrow = n0 + warp_m0 + mi * 16 + rq;
#pragma unroll
                for (int ni = 0; ni < 4; ni++) {
                    const int bcol = warp_n0 + ni * 8 + cq;
                    float* p0 = partbase + (size_t)hrow * 64 + bcol;
                    p0[0] = acc[mi][ni][0];
                    p0[1] = acc[mi][ni][1];
                    float* p1 = p0 + 8 * 64;
                    p1[0] = acc[mi][ni][2];
                    p1[1] = acc[mi][ni][3];
                }
            }
        }
        grid_barrier(want); want ^= 1;

        // fused Euler update
        {
            float4 s0 = *(const float4*)(g_part + ui);
            float4 s1 = *(const float4*)(g_part + (size_t)BH + ui);
            float4 s2 = *(const float4*)(g_part + (size_t)2 * BH + ui);
            float4 s3 = *(const float4*)(g_part + (size_t)3 * BH + ui);
            float4 s4 = *(const float4*)(g_part + (size_t)4 * BH + ui);
            float4 s5 = *(const float4*)(g_part + (size_t)5 * BH + ui);
            float4 s6 = *(const float4*)(g_part + (size_t)6 * BH + ui);
            float4 s7 = *(const float4*)(g_part + (size_t)7 * BH + ui);
            float4 v;
            v.x = 0.9f * hp.x + 0.1f * (s0.x + s1.x + s2.x + s3.x + s4.x + s5.x + s6.x + s7.x + xw.x);
            v.y = 0.9f * hp.y + 0.1f * (s0.y + s1.y + s2.y + s3.y + s4.y + s5.y + s6.y + s7.y + xw.y);
            v.z = 0.9f * hp.z + 0.1f * (s0.z + s1.z + s2.z + s3.z + s4.z + s5.z + s6.z + s7.z + xw.z);
            v.w = 0.9f * hp.w + 0.1f * (s0.w + s1.w + s2.w + s3.w + s4.w + s5.w + s6.w + s7.w + xw.w);
            *(float4*)(g_h + ui) = v;
            float vv[4] = {v.x, v.y, v.z, v.w};
#pragma unroll
            for (int j = 0; j < 4; j++) {
                __stcs(hb + (size_t)j * NS * NH + (size_t)t * NH, vv[j]);
                g_sigh[(size_t)(ub + j) * NH + uh] = __float2half_rn(sigmoidf_(vv[j]));
            }
        }
        grid_barrier(want); want ^= 1;
    }

    // padding barrier -> total 2050 (even): g_flag/g_count end at 0
    grid_barrier(want);
}

// ---------------- k_xw (HMMA): xwn[t][h][b] = x_t @ W_ih^T + 0.1*noise ----------------
// Block (h-tile 128, t). A = W_ih tile (fp16 hi/lo pre-converted), B = x_t fp16.
__global__ void __launch_bounds__(256)
k_xw(const float* __restrict__ x, const float* __restrict__ noise) {
    extern __shared__ __align__(1024) char sm[];
    const uint32_t smb = smem_u32(sm);
    float* noise_s = (float*)(sm + X_NS);
    const int tid = threadIdx.x;
    const int wid = tid >> 5;
    const int lane = tid & 31;
    const int h0 = blockIdx.x * 128;
    const int t  = blockIdx.y;

    const int warp_m0 = (wid >> 1) * 32;
    const int warp_n0 = (wid & 1) * 32;
    const uint32_t aOff = (uint32_t)((warp_m0 + (lane & 15)) * PITCH + ((lane >> 4) << 4));
    const uint32_t aHiA = smb + X_W_HI + aOff;
    const uint32_t aLoA = smb + X_W_LO + aOff;
    const uint32_t bOff = (uint32_t)((warp_n0 + (lane & 7) + ((lane >> 4) << 3)) * PITCH +
                                     (((lane >> 3) & 1) << 4));
    const uint32_t bA = smb + X_B + bOff;

    // stage noise rows [b][128 h-local] fp32 (independent; before first sync)
#pragma unroll
    for (int it = 0; it < 8; it++) {
        const int b = it * 8 + wid;
        float4 nv = *(const float4*)(noise + (size_t)t * BH + (size_t)b * NH + h0 + lane * 4);
        *(float4*)(noise_s + b * 132 + lane * 4) = nv;
    }

    float acc[2][4][4];
#pragma unroll
    for (int mi = 0; mi < 2; mi++)
#pragma unroll
        for (int ni = 0; ni < 4; ni++)
#pragma unroll
            for (int j = 0; j < 4; j++) acc[mi][ni][j] = 0.0f;

    for (int c = 0; c < 2; c++) {   // K = 512 in 2 chunks of 256
        // stage W_ih planes (fp16, pre-converted)
        for (int it = 0; it < 16; it++) {
            const int r = it * 8 + wid;
            uint4 hv = *(const uint4*)(g_wih_hi + (size_t)(h0 + r) * NI + c * 256 + lane * 8);
            uint4 lv = *(const uint4*)(g_wih_lo + (size_t)(h0 + r) * NI + c * 256 + lane * 8);
            *(uint4*)(sm + X_W_HI + r * PITCH + lane * 16) = hv;
            *(uint4*)(sm + X_W_LO + r * PITCH + lane * 16) = lv;
        }
        // stage x_t rows (fp32 -> fp16)
#pragma unroll
        for (int it = 0; it < 8; it++) {
            const int b = it * 8 + wid;
            const float* xr = x + ((size_t)b * NS + t) * NI + c * 256 + lane * 8;
            float4 v0 = *(const float4*)(xr);
            float4 v1 = *(const float4*)(xr + 4);
            uint4 hv = make_uint4(h2pack(v0.x, v0.y), h2pack(v0.z, v0.w),
                                  h2pack(v1.x, v1.y), h2pack(v1.z, v1.w));
            *(uint4*)(sm + X_B + b * PITCH + lane * 16) = hv;
        }
        __syncthreads();
        gemm16(acc, aHiA, aLoA, bA);
        __syncthreads();
    }

    // epilogue: xwn[t][h][b] = acc + 0.1*noise
    const int rq = lane >> 2;
    const int cq = (lane & 3) * 2;
#pragma unroll
    for (int mi = 0; mi < 2; mi++) {
        const int hl = warp_m0 + mi * 16 + rq;       // local h 0..127
#pragma unroll
        for (int ni = 0; ni < 4; ni++) {
            const int b = warp_n0 + ni * 8 + cq;
            float2 v0;
            v0.x = acc[mi][ni][0] + 0.1f * noise_s[(b + 0) * 132 + hl];
            v0.y = acc[mi][ni][1] + 0.1f * noise_s[(b + 1) * 132 + hl];
            *(float2*)(g_xwn + (size_t)t * BH + (size_t)(h0 + hl) * 64 + b) = v0;
            float2 v1;
            v1.x = acc[mi][ni][2] + 0.1f * noise_s[(b + 0) * 132 + hl + 8];
            v1.y = acc[mi][ni][3] + 0.1f * noise_s[(b + 1) * 132 + hl + 8];
            *(float2*)(g_xwn + (size_t)t * BH + (size_t)(h0 + hl + 8) * 64 + b) = v1;
        }
    }
}

// ---------------- k_out (HMMA): out = sigmoid(hidden) @ W_ho^T + b_ho ----------------
// Block (o-tile 128, m-tile 64). A = W_ho tile (fp16 hi/lo), B = sigmoid(hidden) fp16.
__global__ void __launch_bounds__(256)
k_out(const float* __restrict__ hidden, const float* __restrict__ bho,
      float* __restrict__ outp) {
    extern __shared__ __align__(1024) char sm[];
    const uint32_t smb = smem_u32(sm);
    const int tid = threadIdx.x;
    const int wid = tid >> 5;
    const int lane = tid & 31;
    const int o0 = blockIdx.x * 128;
    const int m0 = blockIdx.y * 64;    // 64 consecutive (b,s) rows, same b

    const int warp_m0 = (wid >> 1) * 32;
    const int warp_n0 = (wid & 1) * 32;
    const uint32_t aOff = (uint32_t)((warp_m0 + (lane & 15)) * PITCH + ((lane >> 4) << 4));
    const uint32_t aHiA = smb + O_W_HI + aOff;
    const uint32_t aLoA = smb + O_W_LO + aOff;
    const uint32_t bOff = (uint32_t)((warp_n0 + (lane & 7) + ((lane >> 4) << 3)) * PITCH +
                                     (((lane >> 3) & 1) << 4));
    const uint32_t bA = smb + O_B + bOff;

    float acc[2][4][4];
#pragma unroll
    for (int mi = 0; mi < 2; mi++)
#pragma unroll
        for (int ni = 0; ni < 4; ni++)
#pragma unroll
            for (int j = 0; j < 4; j++) acc[mi][ni][j] = 0.0f;

    for (int c = 0; c < 8; c++) {   // K = 2048 in 8 chunks of 256
        // stage W_ho planes
        for (int it = 0; it < 16; it++) {
            const int r = it * 8 + wid;
            uint4 hv = *(const uint4*)(g_who_hi + (size_t)(o0 + r) * NH + c * 256 + lane * 8);
            uint4 lv = *(const uint4*)(g_who_lo + (size_t)(o0 + r) * NH + c * 256 + lane * 8);
            *(uint4*)(sm + O_W_HI + r * PITCH + lane * 16) = hv;
            *(uint4*)(sm + O_W_LO + r * PITCH + lane * 16) = lv;
        }
        // stage sigmoid(hidden) rows (fp32 -> sigmoid -> fp16)
#pragma unroll
        for (int it = 0; it < 8; it++) {
            const int m = it * 8 + wid;
            const float* hr = hidden + (size_t)(m0 + m) * NH + c * 256 + lane * 8;
            float4 v0 = *(const float4*)(hr);
            float4 v1 = *(const float4*)(hr + 4);
            uint4 hv = make_uint4(
                h2pack(sigmoidf_(v0.x), sigmoidf_(v0.y)),
                h2pack(sigmoidf_(v0.z), sigmoidf_(v0.w)),
                h2pack(sigmoidf_(v1.x), sigmoidf_(v1.y)),
                h2pack(sigmoidf_(v1.z), sigmoidf_(v1.w)));
            *(uint4*)(sm + O_B + m * PITCH + lane * 16) = hv;
        }
        __syncthreads();
        gemm16(acc, aHiA, aLoA, bA);
        __syncthreads();
    }

    // epilogue: out[m][o] = acc + b_ho[o]  (C rows = o, cols = m)
    const int rq = lane >> 2;
    const int cq = (lane & 3) * 2;
#pragma unroll
    for (int mi = 0; mi < 2; mi++) {
        const int o = o0 + warp_m0 + mi * 16 + rq;
        const float bv0 = bho[o];
        const float bv8 = bho[o + 8];
#pragma unroll
        for (int ni = 0; ni < 4; ni++) {
            const int m = m0 + warp_n0 + ni * 8 + cq;
            outp[(size_t)(m + 0) * NO + o] = acc[mi][ni][0] + bv0;
            outp[(size_t)(m + 1) * NO + o] = acc[mi][ni][1] + bv0;
            outp[(size_t)(m + 0) * NO + o + 8] = acc[mi][ni][2] + bv8;
            outp[(size_t)(m + 1) * NO + o + 8] = acc[mi][ni][3] + bv8;
        }
    }
}

extern "C" void kernel_launch(void* const* d_in, const int* in_sizes, int n_in,
                              void* d_out, int out_size) {
    const float* x     = (const float*)d_in[0];   // [B,S,I]
    const float* h0    = (const float*)d_in[1];   // [B,1,H]
    const float* Wih   = (const float*)d_in[2];   // [H,I]
    const float* Whh   = (const float*)d_in[3];   // [H,H]
    const float* Who   = (const float*)d_in[4];   // [O,H]
    const float* bho   = (const float*)d_in[5];   // [O]
    const float* noise = (const float*)d_in[6];   // [S,B,1,H]
    float* outp = (float*)d_out;

    const size_t OUTE = (size_t)NB * NS * NO;
    const size_t HIDE = (size_t)NB * NS * NH;

    float* hidden;
    if ((size_t)out_size >= OUTE + HIDE) {
        hidden = outp + OUTE;   // harness output = concat(out, hidden)
    } else {
        void* p = nullptr;
        cudaGetSymbolAddress(&p, g_hid_fb);
        hidden = (float*)p;
    }

    cudaFuncSetAttribute(k_recur, cudaFuncAttributeMaxDynamicSharedMemorySize, R_TOTAL);
    cudaFuncSetAttribute(k_xw, cudaFuncAttributeMaxDynamicSharedMemorySize, X_TOTAL);
    cudaFuncSetAttribute(k_out, cudaFuncAttributeMaxDynamicSharedMemorySize, O_TOTAL);

    // 0. one-time weight conversion (fp32 -> fp16 hi/lo planes)
    k_convW<<<(NH * NI + NO * NH) / 256, 256>>>(Wih, Who);

    // 1. input projection (HMMA) + noise fold, layout [t][h][b]
    k_xw<<<dim3(NH / 128, NS), 256, X_TOTAL>>>(x, noise);

    // 2. full recurrence: persistent HMMA kernel
    k_recur<<<GB, 256, R_TOTAL>>>(h0, Whh, hidden);

    // 3. output projection (HMMA)
    k_out<<<dim3(NO / 128, (NB * NS) / 64), 256, O_TOTAL>>>(hidden, bho, outp);
}

// round 8
// speedup vs baseline: 2.8428x; 1.2269x over previous
#include <cuda_runtime.h>
#include <cuda_fp16.h>
#include <cstdint>

// ---------------- problem constants ----------------
namespace {
constexpr int NB = 64;     // batch
constexpr int NS = 1024;   // sequence length
constexpr int NI = 512;    // input dim
constexpr int NH = 2048;   // hidden dim
constexpr int NO = 512;    // output dim
constexpr int BH = NB * NH;      // 131072 state elements

constexpr int GB = 128;          // persistent blocks (1/SM, co-resident)
constexpr int SK = 8;            // split-K chunks (recurrence)
constexpr int KC = NH / SK;      // 256 K per recurrence block

// smem tile pitch: 512B of K data + 16B pad -> conflict-free ldmatrix
constexpr int PITCH = 528;

// k_recur smem layout (single fp16 plane for W)
constexpr int R_W = 0;                       // 128 rows
constexpr int R_B = R_W + 128 * PITCH;       // 64 rows
constexpr int R_TOTAL = R_B + 64 * PITCH;    // ~101 KB

// k_xw smem layout
constexpr int X_W  = 0;
constexpr int X_B  = X_W + 128 * PITCH;
constexpr int X_NS = X_B + 64 * PITCH;       // 64 rows x 132 floats
constexpr int X_TOTAL = X_NS + 64 * 132 * 4; // ~135 KB

// k_out smem layout
constexpr int O_W = 0;
constexpr int O_B = O_W + 128 * PITCH;
constexpr int O_TOTAL = O_B + 64 * PITCH;    // ~101 KB
}

// ---------------- scratch (static device allocations) ----------------
__device__ float g_xwn[(size_t)NS * NB * NH];     // [t][h][b] xw + 0.1*noise
__device__ float g_hid_fb[(size_t)NB * NS * NH];  // fallback hidden storage
__device__ float g_part[(size_t)SK * BH];         // partials, writer-contiguous layout
__device__ __half g_sigh[BH];                     // sigmoid(h) fp16 [b][h]
__device__ __half g_wih[(size_t)NH * NI];         // W_ih fp16 [h][i]
__device__ __half g_who[(size_t)NO * NH];         // W_ho fp16 [o][h]

// grid-barrier state (returns to all-zero at end of every launch)
__device__ unsigned g_slots[GB];
__device__ unsigned g_flag;

// ---------------- helpers ----------------
__device__ __forceinline__ float sigmoidf_(float x) {
    return 1.0f / (1.0f + __expf(-x));
}
__device__ __forceinline__ unsigned h2pack(float a, float b) {
    __half2 t;
    t.x = __float2half_rn(a);
    t.y = __float2half_rn(b);
    return *reinterpret_cast<unsigned*>(&t);
}
__device__ __forceinline__ uint32_t smem_u32(const void* p) {
    uint32_t a;
    asm("{ .reg .u64 t; cvta.to.shared.u64 t, %1; cvt.u32.u64 %0, t; }"
        : "=r"(a) : "l"(p));
    return a;
}
// ldmatrix stays volatile (must not hoist above __syncthreads)
__device__ __forceinline__ void ldsm4(unsigned* r, uint32_t addr) {
    asm volatile("ldmatrix.sync.aligned.m8n8.x4.shared.b16 {%0,%1,%2,%3}, [%4];"
                 : "=r"(r[0]), "=r"(r[1]), "=r"(r[2]), "=r"(r[3]) : "r"(addr));
}
// MMA is NON-volatile: pure register op; lets ptxas interleave for ILP
__device__ __forceinline__ void mma_f16(float* d, const unsigned* a, const unsigned* b) {
    asm("mma.sync.aligned.m16n8k16.row.col.f32.f16.f16.f32 "
        "{%0,%1,%2,%3}, {%4,%5,%6,%7}, {%8,%9}, {%0,%1,%2,%3};"
        : "+f"(d[0]), "+f"(d[1]), "+f"(d[2]), "+f"(d[3])
        : "r"(a[0]), "r"(a[1]), "r"(a[2]), "r"(a[3]), "r"(b[0]), "r"(b[1]));
}

// Shared inner GEMM (single fp16 plane): 16 k-steps over staged A[128x256] /
// B[64x256]; warp computes its m32 x n32 tile. 8 independent accumulator chains.
__device__ __forceinline__ void gemm16(float acc[2][4][4], uint32_t aA, uint32_t bA) {
#pragma unroll 4
    for (int ks = 0; ks < 16; ks++) {
        const uint32_t ko = ks * 32;
        unsigned am[2][4], bm[4][2];
        ldsm4(am[0], aA + ko);
        ldsm4(am[1], aA + ko + 16 * PITCH);
        ldsm4(&bm[0][0], bA + ko);
        ldsm4(&bm[2][0], bA + ko + 16 * PITCH);
#pragma unroll
        for (int mi = 0; mi < 2; mi++)
#pragma unroll
            for (int ni = 0; ni < 4; ni++)
                mma_f16(acc[mi][ni], am[mi], bm[ni]);
    }
}

// ---------------- flag-array grid barrier (sense reversal, no atomics) ----------------
// Every block release-stores its sense slot; block 0 gathers all 128 slots in
// parallel (one thread per slot), then release-stores the broadcast flag.
// Sense alternates 1,0,1,... per barrier; even total count per launch -> all
// state returns to 0 (graph-replay safe).
__device__ __forceinline__ void grid_barrier(unsigned want) {
    __syncthreads();
    if (threadIdx.x == 0) {
        asm volatile("st.release.gpu.global.u32 [%0], %1;"
                     :: "l"(&g_slots[blockIdx.x]), "r"(want) : "memory");
    }
    if (blockIdx.x == 0) {
        if (threadIdx.x < GB) {
            unsigned v;
            do {
                asm volatile("ld.acquire.gpu.global.u32 %0, [%1];"
                             : "=r"(v) : "l"(&g_slots[threadIdx.x]) : "memory");
            } while (v != want);
        }
        __syncthreads();
        if (threadIdx.x == 0) {
            asm volatile("st.release.gpu.global.u32 [%0], %1;"
                         :: "l"(&g_flag), "r"(want) : "memory");
        }
    } else {
        if (threadIdx.x == 0) {
            unsigned v;
            do {
                asm volatile("ld.acquire.gpu.global.u32 %0, [%1];"
                             : "=r"(v) : "l"(&g_flag) : "memory");
            } while (v != want);
        }
        __syncthreads();
    }
}

// ---------------- W_ih / W_ho fp32 -> fp16 conversion (one-time) ----------------
__global__ void __launch_bounds__(256) k_convW(const float* __restrict__ Wih,
                                               const float* __restrict__ Who) {
    const int idx = blockIdx.x * 256 + threadIdx.x;
    if (idx < NH * NI) {
        g_wih[idx] = __float2half_rn(Wih[idx]);
    } else {
        int i = idx - NH * NI;
        g_who[i] = __float2half_rn(Who[i]);
    }
}

// ---------------- persistent recurrence kernel ----------------
// Block (nt, sk): D[128 h-rows, 64 b] = Whh_f16[nt*128.., kchunk] x sigh[b, kchunk]^T
// W chunk staged once in SMEM; sigh tile restaged per step.
// g_part layout: plane sk, region nt (8192 floats), thread-contiguous 32 floats.
__global__ void __launch_bounds__(256, 1)
k_recur(const float* __restrict__ h0, const float* __restrict__ Whh,
        float* __restrict__ hidden) {
    extern __shared__ __align__(1024) char sm[];
    const uint32_t smb = smem_u32(sm);
    const int tid = threadIdx.x;
    const int wid = tid >> 5;
    const int lane = tid & 31;
    const int bx = blockIdx.x;
    const int nt = bx >> 3;            // 0..15
    const int sk = bx & 7;             // 0..7
    const int n0 = nt * 128;           // W row base (h)
    const int kbeg = sk * KC;          // K chunk base

    // ---- one-time: stage W_hh chunk as fp16 into SMEM ----
    for (int it = 0; it < 16; it++) {
        const int r = it * 8 + wid;                     // 0..127
        const float* wrow = Whh + (size_t)(n0 + r) * NH + kbeg + lane * 8;
        float4 v0 = *(const float4*)(wrow);
        float4 v1 = *(const float4*)(wrow + 4);
        uint4 H = make_uint4(h2pack(v0.x, v0.y), h2pack(v0.z, v0.w),
                             h2pack(v1.x, v1.y), h2pack(v1.z, v1.w));
        *(uint4*)(sm + R_W + r * PITCH + lane * 16) = H;
    }

    // ---- update-phase (h,b) mapping: inverse of writer-contiguous layout ----
    const int f = (bx << 10) + (tid << 2);    // flat partial index, float4-aligned
    const int ntu = f >> 13;                  // writer region
    const int w = (f >> 5) & 255;             // writer thread
    const int j0 = f & 31;
    const int mi_u = j0 >> 4, ni_u = (j0 >> 2) & 3;
    const int wwid = w >> 5, wlane = w & 31;
    const int h = ntu * 128 + ((wwid >> 1) << 5) + mi_u * 16 + (wlane >> 2);
    const int b = ((wwid & 1) << 5) + ni_u * 8 + ((wlane & 3) << 1);
    // this thread's 4 state elements: (h,b), (h,b+1), (h+8,b), (h+8,b+1)

    // ---- init state: h in REGISTERS, sigh fp16 [b][h] in global ----
    float4 hp;
    hp.x = h0[(size_t)(b + 0) * NH + h];
    hp.y = h0[(size_t)(b + 1) * NH + h];
    hp.z = h0[(size_t)(b + 0) * NH + h + 8];
    hp.w = h0[(size_t)(b + 1) * NH + h + 8];
    g_sigh[(size_t)(b + 0) * NH + h] = __float2half_rn(sigmoidf_(hp.x));
    g_sigh[(size_t)(b + 1) * NH + h] = __float2half_rn(sigmoidf_(hp.y));
    g_sigh[(size_t)(b + 0) * NH + h + 8] = __float2half_rn(sigmoidf_(hp.z));
    g_sigh[(size_t)(b + 1) * NH + h + 8] = __float2half_rn(sigmoidf_(hp.w));

    unsigned want = 1;
    grid_barrier(want); want ^= 1;   // barrier #1

    // ---- per-thread GEMM constants ----
    const int warp_m0 = (wid >> 1) * 32;       // W-row tile of this warp
    const int warp_n0 = (wid & 1) * 32;        // batch tile of this warp
    const uint32_t aA = smb + R_W +
        (uint32_t)((warp_m0 + (lane & 15)) * PITCH + ((lane >> 4) << 4));
    const uint32_t bA = smb + R_B +
        (uint32_t)((warp_n0 + (lane & 7) + ((lane >> 4) << 3)) * PITCH +
                   (((lane >> 3) & 1) << 4));

    float* pout = g_part + (size_t)sk * BH + (size_t)nt * 8192 + tid * 32;
    float* hid0 = hidden + (size_t)(b + 0) * NS * NH + h;
    float* hid1 = hidden + (size_t)(b + 1) * NS * NH + h;

    for (int t = 0; t < NS; t++) {
        // prefetch update-phase xw operands (hide DRAM latency behind GEMM)
        const float2 x0 = __ldcs((const float2*)(g_xwn + (size_t)t * BH + (size_t)h * 64 + b));
        const float2 x1 = __ldcs((const float2*)(g_xwn + (size_t)t * BH + (size_t)(h + 8) * 64 + b));

        // stage sigh tile (fp16) into SMEM
#pragma unroll
        for (int it = 0; it < 8; it++) {
            const int r = it * 8 + wid;   // batch row 0..63
            uint4 hv = *(const uint4*)(g_sigh + (size_t)r * NH + kbeg + lane * 8);
            *(uint4*)(sm + R_B + r * PITCH + lane * 16) = hv;
        }
        __syncthreads();

        float acc[2][4][4];
#pragma unroll
        for (int mi = 0; mi < 2; mi++)
#pragma unroll
            for (int ni = 0; ni < 4; ni++)
#pragma unroll
                for (int j = 0; j < 4; j++) acc[mi][ni][j] = 0.0f;

        gemm16(acc, aA, bA);
        __syncthreads();   // smem reads done before next-step restage

        // epilogue: thread-contiguous partial stores (fully coalesced)
#pragma unroll
        for (int mi = 0; mi < 2; mi++)
#pragma unroll
            for (int ni = 0; ni < 4; ni++)
                *(float4*)(pout + mi * 16 + ni * 4) = *(const float4*)acc[mi][ni];

        grid_barrier(want); want ^= 1;

        // fused Euler update (h state lives in registers)
        {
            float4 s0 = *(const float4*)(g_part + f);
            float4 s1 = *(const float4*)(g_part + (size_t)BH + f);
            float4 s2 = *(const float4*)(g_part + (size_t)2 * BH + f);
            float4 s3 = *(const float4*)(g_part + (size_t)3 * BH + f);
            float4 s4 = *(const float4*)(g_part + (size_t)4 * BH + f);
            float4 s5 = *(const float4*)(g_part + (size_t)5 * BH + f);
            float4 s6 = *(const float4*)(g_part + (size_t)6 * BH + f);
            float4 s7 = *(const float4*)(g_part + (size_t)7 * BH + f);
            float4 v;
            v.x = 0.9f * hp.x + 0.1f * (s0.x + s1.x + s2.x + s3.x + s4.x + s5.x + s6.x + s7.x + x0.x);
            v.y = 0.9f * hp.y + 0.1f * (s0.y + s1.y + s2.y + s3.y + s4.y + s5.y + s6.y + s7.y + x0.y);
            v.z = 0.9f * hp.z + 0.1f * (s0.z + s1.z + s2.z + s3.z + s4.z + s5.z + s6.z + s7.z + x1.x);
            v.w = 0.9f * hp.w + 0.1f * (s0.w + s1.w + s2.w + s3.w + s4.w + s5.w + s6.w + s7.w + x1.y);
            hp = v;
            __stcs(hid0 + (size_t)t * NH, v.x);
            __stcs(hid1 + (size_t)t * NH, v.y);
            __stcs(hid0 + (size_t)t * NH + 8, v.z);
            __stcs(hid1 + (size_t)t * NH + 8, v.w);
            g_sigh[(size_t)(b + 0) * NH + h] = __float2half_rn(sigmoidf_(v.x));
            g_sigh[(size_t)(b + 1) * NH + h] = __float2half_rn(sigmoidf_(v.y));
            g_sigh[(size_t)(b + 0) * NH + h + 8] = __float2half_rn(sigmoidf_(v.z));
            g_sigh[(size_t)(b + 1) * NH + h + 8] = __float2half_rn(sigmoidf_(v.w));
        }
        grid_barrier(want); want ^= 1;
    }

    // padding barrier -> total 2050 (even): g_slots/g_flag end at 0
    grid_barrier(want);
}

// ---------------- k_xw (HMMA): xwn[t][h][b] = x_t @ W_ih^T + 0.1*noise ----------------
__global__ void __launch_bounds__(256)
k_xw(const float* __restrict__ x, const float* __restrict__ noise) {
    extern __shared__ __align__(1024) char sm[];
    const uint32_t smb = smem_u32(sm);
    float* noise_s = (float*)(sm + X_NS);
    const int tid = threadIdx.x;
    const int wid = tid >> 5;
    const int lane = tid & 31;
    const int h0 = blockIdx.x * 128;
    const int t  = blockIdx.y;

    const int warp_m0 = (wid >> 1) * 32;
    const int warp_n0 = (wid & 1) * 32;
    const uint32_t aA = smb + X_W +
        (uint32_t)((warp_m0 + (lane & 15)) * PITCH + ((lane >> 4) << 4));
    const uint32_t bA = smb + X_B +
        (uint32_t)((warp_n0 + (lane & 7) + ((lane >> 4) << 3)) * PITCH +
                   (((lane >> 3) & 1) << 4));

    // stage noise rows [b][128 h-local] fp32
#pragma unroll
    for (int it = 0; it < 8; it++) {
        const int b = it * 8 + wid;
        float4 nv = *(const float4*)(noise + (size_t)t * BH + (size_t)b * NH + h0 + lane * 4);
        *(float4*)(noise_s + b * 132 + lane * 4) = nv;
    }

    float acc[2][4][4];
#pragma unroll
    for (int mi = 0; mi < 2; mi++)
#pragma unroll
        for (int ni = 0; ni < 4; ni++)
#pragma unroll
            for (int j = 0; j < 4; j++) acc[mi][ni][j] = 0.0f;

    for (int c = 0; c < 2; c++) {   // K = 512 in 2 chunks of 256
        for (int it = 0; it < 16; it++) {
            const int r = it * 8 + wid;
            uint4 hv = *(const uint4*)(g_wih + (size_t)(h0 + r) * NI + c * 256 + lane * 8);
            *(uint4*)(sm + X_W + r * PITCH + lane * 16) = hv;
        }
#pragma unroll
        for (int it = 0; it < 8; it++) {
            const int b = it * 8 + wid;
            const float* xr = x + ((size_t)b * NS + t) * NI + c * 256 + lane * 8;
            float4 v0 = *(const float4*)(xr);
            float4 v1 = *(const float4*)(xr + 4);
            uint4 hv = make_uint4(h2pack(v0.x, v0.y), h2pack(v0.z, v0.w),
                                  h2pack(v1.x, v1.y), h2pack(v1.z, v1.w));
            *(uint4*)(sm + X_B + b * PITCH + lane * 16) = hv;
        }
        __syncthreads();
        gemm16(acc, aA, bA);
        __syncthreads();
    }

    // epilogue: xwn[t][h][b] = acc + 0.1*noise
    const int rq = lane >> 2;
    const int cq = (lane & 3) * 2;
#pragma unroll
    for (int mi = 0; mi < 2; mi++) {
        const int hl = warp_m0 + mi * 16 + rq;       // local h 0..127
#pragma unroll
        for (int ni = 0; ni < 4; ni++) {
            const int b = warp_n0 + ni * 8 + cq;
            float2 v0;
            v0.x = acc[mi][ni][0] + 0.1f * noise_s[(b + 0) * 132 + hl];
            v0.y = acc[mi][ni][1] + 0.1f * noise_s[(b + 1) * 132 + hl];
            *(float2*)(g_xwn + (size_t)t * BH + (size_t)(h0 + hl) * 64 + b) = v0;
            float2 v1;
            v1.x = acc[mi][ni][2] + 0.1f * noise_s[(b + 0) * 132 + hl + 8];
            v1.y = acc[mi][ni][3] + 0.1f * noise_s[(b + 1) * 132 + hl + 8];
            *(float2*)(g_xwn + (size_t)t * BH + (size_t)(h0 + hl + 8) * 64 + b) = v1;
        }
    }
}

// ---------------- k_out (HMMA): out = sigmoid(hidden) @ W_ho^T + b_ho ----------------
__global__ void __launch_bounds__(256)
k_out(const float* __restrict__ hidden, const float* __restrict__ bho,
      float* __restrict__ outp) {
    extern __shared__ __align__(1024) char sm[];
    const uint32_t smb = smem_u32(sm);
    const int tid = threadIdx.x;
    const int wid = tid >> 5;
    const int lane = tid & 31;
    const int o0 = blockIdx.x * 128;
    const int m0 = blockIdx.y * 64;

    const int warp_m0 = (wid >> 1) * 32;
    const int warp_n0 = (wid & 1) * 32;
    const uint32_t aA = smb + O_W +
        (uint32_t)((warp_m0 + (lane & 15)) * PITCH + ((lane >> 4) << 4));
    const uint32_t bA = smb + O_B +
        (uint32_t)((warp_n0 + (lane & 7) + ((lane >> 4) << 3)) * PITCH +
                   (((lane >> 3) & 1) << 4));

    float acc[2][4][4];
#pragma unroll
    for (int mi = 0; mi < 2; mi++)
#pragma unroll
        for (int ni = 0; ni < 4; ni++)
#pragma unroll
            for (int j = 0; j < 4; j++) acc[mi][ni][j] = 0.0f;

    for (int c = 0; c < 8; c++) {   // K = 2048 in 8 chunks of 256
        for (int it = 0; it < 16; it++) {
            const int r = it * 8 + wid;
            uint4 hv = *(const uint4*)(g_who + (size_t)(o0 + r) * NH + c * 256 + lane * 8);
            *(uint4*)(sm + O_W + r * PITCH + lane * 16) = hv;
        }
#pragma unroll
        for (int it = 0; it < 8; it++) {
            const int m = it * 8 + wid;
            const float* hr = hidden + (size_t)(m0 + m) * NH + c * 256 + lane * 8;
            float4 v0 = *(const float4*)(hr);
            float4 v1 = *(const float4*)(hr + 4);
            uint4 hv = make_uint4(
                h2pack(sigmoidf_(v0.x), sigmoidf_(v0.y)),
                h2pack(sigmoidf_(v0.z), sigmoidf_(v0.w)),
                h2pack(sigmoidf_(v1.x), sigmoidf_(v1.y)),
                h2pack(sigmoidf_(v1.z), sigmoidf_(v1.w)));
            *(uint4*)(sm + O_B + m * PITCH + lane * 16) = hv;
        }
        __syncthreads();
        gemm16(acc, aA, bA);
        __syncthreads();
    }

    const int rq = lane >> 2;
    const int cq = (lane & 3) * 2;
#pragma unroll
    for (int mi = 0; mi < 2; mi++) {
        const int o = o0 + warp_m0 + mi * 16 + rq;
        const float bv0 = bho[o];
        const float bv8 = bho[o + 8];
#pragma unroll
        for (int ni = 0; ni < 4; ni++) {
            const int m = m0 + warp_n0 + ni * 8 + cq;
            outp[(size_t)(m + 0) * NO + o] = acc[mi][ni][0] + bv0;
            outp[(size_t)(m + 1) * NO + o] = acc[mi][ni][1] + bv0;
            outp[(size_t)(m + 0) * NO + o + 8] = acc[mi][ni][2] + bv8;
            outp[(size_t)(m + 1) * NO + o + 8] = acc[mi][ni][3] + bv8;
        }
    }
}

extern "C" void kernel_launch(void* const* d_in, const int* in_sizes, int n_in,
                              void* d_out, int out_size) {
    const float* x     = (const float*)d_in[0];   // [B,S,I]
    const float* h0    = (const float*)d_in[1];   // [B,1,H]
    const float* Wih   = (const float*)d_in[2];   // [H,I]
    const float* Whh   = (const float*)d_in[3];   // [H,H]
    const float* Who   = (const float*)d_in[4];   // [O,H]
    const float* bho   = (const float*)d_in[5];   // [O]
    const float* noise = (const float*)d_in[6];   // [S,B,1,H]
    float* outp = (float*)d_out;

    const size_t OUTE = (size_t)NB * NS * NO;
    const size_t HIDE = (size_t)NB * NS * NH;

    float* hidden;
    if ((size_t)out_size >= OUTE + HIDE) {
        hidden = outp + OUTE;   // harness output = concat(out, hidden)
    } else {
        void* p = nullptr;
        cudaGetSymbolAddress(&p, g_hid_fb);
        hidden = (float*)p;
    }

    cudaFuncSetAttribute(k_recur, cudaFuncAttributeMaxDynamicSharedMemorySize, R_TOTAL);
    cudaFuncSetAttribute(k_xw, cudaFuncAttributeMaxDynamicSharedMemorySize, X_TOTAL);
    cudaFuncSetAttribute(k_out, cudaFuncAttributeMaxDynamicSharedMemorySize, O_TOTAL);

    // 0. one-time weight conversion (fp32 -> fp16)
    k_convW<<<(NH * NI + NO * NH) / 256, 256>>>(Wih, Who);

    // 1. input projection (HMMA) + noise fold, layout [t][h][b]
    k_xw<<<dim3(NH / 128, NS), 256, X_TOTAL>>>(x, noise);

    // 2. full recurrence: persistent HMMA kernel
    k_recur<<<GB, 256, R_TOTAL>>>(h0, Whh, hidden);

    // 3. output projection (HMMA)
    k_out<<<dim3(NO / 128, (NB * NS) / 64), 256, O_TOTAL>>>(hidden, bho, outp);
}

// round 9
// speedup vs baseline: 3.4295x; 1.2064x over previous
#include <cuda_runtime.h>
#include <cuda_fp16.h>
#include <cstdint>

// ---------------- problem constants ----------------
namespace {
constexpr int NB = 64;     // batch
constexpr int NS = 1024;   // sequence length
constexpr int NI = 512;    // input dim
constexpr int NH = 2048;   // hidden dim
constexpr int NO = 512;    // output dim
constexpr int BH = NB * NH;      // 131072 state elements

constexpr int GB = 128;          // persistent blocks (1/SM, co-resident)
constexpr int SK = 8;            // split-K chunks (recurrence)
constexpr int KC = NH / SK;      // 256 K per recurrence block

// smem tile pitch: 512B of K data + 16B pad -> conflict-free ldmatrix
constexpr int PITCH = 528;

// k_recur smem layout (single fp16 plane for W)
constexpr int R_W = 0;                       // 128 rows
constexpr int R_B = R_W + 128 * PITCH;       // 64 rows
constexpr int R_TOTAL = R_B + 64 * PITCH;    // ~101 KB

// k_xw smem layout
constexpr int X_W  = 0;
constexpr int X_B  = X_W + 128 * PITCH;
constexpr int X_NS = X_B + 64 * PITCH;       // 64 rows x 132 floats
constexpr int X_TOTAL = X_NS + 64 * 132 * 4; // ~135 KB

// k_out smem layout
constexpr int O_W = 0;
constexpr int O_B = O_W + 128 * PITCH;
constexpr int O_TOTAL = O_B + 64 * PITCH;    // ~101 KB

// counter rows: 0-15 band, 16-23 stage, 24-39 pread, 40-47 chunk
constexpr int C_BAND  = 0;
constexpr int C_STAGE = 16;
constexpr int C_PREAD = 24;
constexpr int C_CHUNK = 40;
}

// ---------------- scratch (static device allocations) ----------------
__device__ float g_xwn[(size_t)NS * NB * NH];     // [t][h][b] xw + 0.1*noise
__device__ float g_hid_fb[(size_t)NB * NS * NH];  // fallback hidden storage
__device__ float g_part[(size_t)SK * BH];         // partials, writer-contiguous layout
__device__ __half g_sigh[BH];                     // sigmoid(h) fp16 [b][h]
__device__ __half g_wih[(size_t)NH * NI];         // W_ih fp16 [h][i]
__device__ __half g_who[(size_t)NO * NH];         // W_ho fp16 [o][h]

// sync state: flag barrier (self-cleaning) + monotonic counters (reset at launch)
__device__ unsigned g_slots[GB];
__device__ unsigned g_flag;
__device__ unsigned g_cnt[48][8];   // 32B-strided counters

// ---------------- helpers ----------------
__device__ __forceinline__ float sigmoidf_(float x) {
    return 1.0f / (1.0f + __expf(-x));
}
__device__ __forceinline__ unsigned h2pack(float a, float b) {
    __half2 t;
    t.x = __float2half_rn(a);
    t.y = __float2half_rn(b);
    return *reinterpret_cast<unsigned*>(&t);
}
__device__ __forceinline__ uint32_t smem_u32(const void* p) {
    uint32_t a;
    asm("{ .reg .u64 t; cvta.to.shared.u64 t, %1; cvt.u32.u64 %0, t; }"
        : "=r"(a) : "l"(p));
    return a;
}
__device__ __forceinline__ void ldsm4(unsigned* r, uint32_t addr) {
    asm volatile("ldmatrix.sync.aligned.m8n8.x4.shared.b16 {%0,%1,%2,%3}, [%4];"
                 : "=r"(r[0]), "=r"(r[1]), "=r"(r[2]), "=r"(r[3]) : "r"(addr));
}
__device__ __forceinline__ void mma_f16(float* d, const unsigned* a, const unsigned* b) {
    asm("mma.sync.aligned.m16n8k16.row.col.f32.f16.f16.f32 "
        "{%0,%1,%2,%3}, {%4,%5,%6,%7}, {%8,%9}, {%0,%1,%2,%3};"
        : "+f"(d[0]), "+f"(d[1]), "+f"(d[2]), "+f"(d[3])
        : "r"(a[0]), "r"(a[1]), "r"(a[2]), "r"(a[3]), "r"(b[0]), "r"(b[1]));
}

__device__ __forceinline__ void gemm16(float acc[2][4][4], uint32_t aA, uint32_t bA) {
#pragma unroll 4
    for (int ks = 0; ks < 16; ks++) {
        const uint32_t ko = ks * 32;
        unsigned am[2][4], bm[4][2];
        ldsm4(am[0], aA + ko);
        ldsm4(am[1], aA + ko + 16 * PITCH);
        ldsm4(&bm[0][0], bA + ko);
        ldsm4(&bm[2][0], bA + ko + 16 * PITCH);
#pragma unroll
        for (int mi = 0; mi < 2; mi++)
#pragma unroll
            for (int ni = 0; ni < 4; ni++)
                mma_f16(acc[mi][ni], am[mi], bm[ni]);
    }
}

// ---------------- sparse sync primitives ----------------
__device__ __forceinline__ void arrive(unsigned* p) {
    asm volatile("red.release.gpu.global.add.u32 [%0], %1;"
                 :: "l"(p), "r"(1u) : "memory");
}
__device__ __forceinline__ void pollge(unsigned* p, unsigned target) {
    unsigned v;
    do {
        asm volatile("ld.acquire.gpu.global.u32 %0, [%1];"
                     : "=r"(v) : "l"(p) : "memory");
    } while (v < target);
}

// flag-array full barrier (used twice per launch; state returns to 0)
__device__ __forceinline__ void flag_barrier(unsigned want) {
    __syncthreads();
    if (threadIdx.x == 0) {
        asm volatile("st.release.gpu.global.u32 [%0], %1;"
                     :: "l"(&g_slots[blockIdx.x]), "r"(want) : "memory");
    }
    if (blockIdx.x == 0) {
        if (threadIdx.x < GB) {
            unsigned v;
            do {
                asm volatile("ld.acquire.gpu.global.u32 %0, [%1];"
                             : "=r"(v) : "l"(&g_slots[threadIdx.x]) : "memory");
            } while (v != want);
        }
        __syncthreads();
        if (threadIdx.x == 0) {
            asm volatile("st.release.gpu.global.u32 [%0], %1;"
                         :: "l"(&g_flag), "r"(want) : "memory");
        }
    } else {
        if (threadIdx.x == 0) {
            unsigned v;
            do {
                asm volatile("ld.acquire.gpu.global.u32 %0, [%1];"
                             : "=r"(v) : "l"(&g_flag) : "memory");
            } while (v != want);
        }
        __syncthreads();
    }
}

// ---------------- W_ih / W_ho fp32 -> fp16 conversion (one-time) ----------------
__global__ void __launch_bounds__(256) k_convW(const float* __restrict__ Wih,
                                               const float* __restrict__ Who) {
    const int idx = blockIdx.x * 256 + threadIdx.x;
    if (idx < NH * NI) {
        g_wih[idx] = __float2half_rn(Wih[idx]);
    } else {
        int i = idx - NH * NI;
        g_who[i] = __float2half_rn(Who[i]);
    }
}

// ---------------- persistent recurrence kernel (sparse sync) ----------------
__global__ void __launch_bounds__(256, 1)
k_recur(const float* __restrict__ h0, const float* __restrict__ Whh,
        float* __restrict__ hidden) {
    extern __shared__ __align__(1024) char sm[];
    const uint32_t smb = smem_u32(sm);
    const int tid = threadIdx.x;
    const int wid = tid >> 5;
    const int lane = tid & 31;
    const int bx = blockIdx.x;
    const int nt = bx >> 3;            // 0..15  (128-row h band)
    const int sk = bx & 7;             // 0..7   (k chunk consumed)
    const int n0 = nt * 128;
    const int kbeg = sk * KC;
    const int my_chunk = nt >> 1;      // chunk this block's updates feed

    // counter reset (visibility guaranteed by flag_barrier release below)
    if (bx == 0 && tid < 48) g_cnt[tid][0] = 0;

    // ---- one-time: stage W_hh chunk as fp16 into SMEM ----
    for (int it = 0; it < 16; it++) {
        const int r = it * 8 + wid;
        const float* wrow = Whh + (size_t)(n0 + r) * NH + kbeg + lane * 8;
        float4 v0 = *(const float4*)(wrow);
        float4 v1 = *(const float4*)(wrow + 4);
        uint4 H = make_uint4(h2pack(v0.x, v0.y), h2pack(v0.z, v0.w),
                             h2pack(v1.x, v1.y), h2pack(v1.z, v1.w));
        *(uint4*)(sm + R_W + r * PITCH + lane * 16) = H;
    }

    // ---- update-phase (h,b) mapping (inverse of writer-contiguous layout) ----
    const int f = (bx << 10) + (tid << 2);
    const int ntu = f >> 13;
    const int w = (f >> 5) & 255;
    const int j0 = f & 31;
    const int mi_u = j0 >> 4, ni_u = (j0 >> 2) & 3;
    const int wwid = w >> 5, wlane = w & 31;
    const int h = ntu * 128 + ((wwid >> 1) << 5) + mi_u * 16 + (wlane >> 2);
    const int b = ((wwid & 1) << 5) + ni_u * 8 + ((wlane & 3) << 1);

    // ---- init state: h in registers, sigh fp16 [b][h] in global ----
    float4 hp;
    hp.x = h0[(size_t)(b + 0) * NH + h];
    hp.y = h0[(size_t)(b + 1) * NH + h];
    hp.z = h0[(size_t)(b + 0) * NH + h + 8];
    hp.w = h0[(size_t)(b + 1) * NH + h + 8];
    g_sigh[(size_t)(b + 0) * NH + h] = __float2half_rn(sigmoidf_(hp.x));
    g_sigh[(size_t)(b + 1) * NH + h] = __float2half_rn(sigmoidf_(hp.y));
    g_sigh[(size_t)(b + 0) * NH + h + 8] = __float2half_rn(sigmoidf_(hp.z));
    g_sigh[(size_t)(b + 1) * NH + h + 8] = __float2half_rn(sigmoidf_(hp.w));

    flag_barrier(1);   // counters reset + init sigh visible everywhere

    // ---- per-thread GEMM constants ----
    const int warp_m0 = (wid >> 1) * 32;
    const int warp_n0 = (wid & 1) * 32;
    const uint32_t aA = smb + R_W +
        (uint32_t)((warp_m0 + (lane & 15)) * PITCH + ((lane >> 4) << 4));
    const uint32_t bA = smb + R_B +
        (uint32_t)((warp_n0 + (lane & 7) + ((lane >> 4) << 3)) * PITCH +
                   (((lane >> 3) & 1) << 4));

    float* pout = g_part + (size_t)sk * BH + (size_t)nt * 8192 + tid * 32;
    float* hid0 = hidden + (size_t)(b + 0) * NS * NH + h;
    float* hid1 = hidden + (size_t)(b + 1) * NS * NH + h;

    for (int t = 0; t < NS; t++) {
        // prefetch update-phase xw operands
        const float2 x0 = __ldcs((const float2*)(g_xwn + (size_t)t * BH + (size_t)h * 64 + b));
        const float2 x1 = __ldcs((const float2*)(g_xwn + (size_t)t * BH + (size_t)(h + 8) * 64 + b));

        // phase 1: wait sigh(t) for my chunk (RAW) + partial readers done (WAR)
        if (tid == 0)  pollge(&g_cnt[C_CHUNK + sk][0], 16u * (unsigned)t);
        if (tid == 32) pollge(&g_cnt[C_PREAD + nt][0], 8u * (unsigned)t);
        __syncthreads();

        // phase 2: stage sigh tile (fp16) into SMEM
#pragma unroll
        for (int it = 0; it < 8; it++) {
            const int r = it * 8 + wid;
            uint4 hv = *(const uint4*)(g_sigh + (size_t)r * NH + kbeg + lane * 8);
            *(uint4*)(sm + R_B + r * PITCH + lane * 16) = hv;
        }
        __syncthreads();
        if (tid == 0) arrive(&g_cnt[C_STAGE + sk][0]);   // done reading sigh(t)

        // phase 3: GEMM
        float acc[2][4][4];
#pragma unroll
        for (int mi = 0; mi < 2; mi++)
#pragma unroll
            for (int ni = 0; ni < 4; ni++)
#pragma unroll
                for (int j = 0; j < 4; j++) acc[mi][ni][j] = 0.0f;
        gemm16(acc, aA, bA);

        // phase 4: epilogue (thread-contiguous partial stores) + band arrive
#pragma unroll
        for (int mi = 0; mi < 2; mi++)
#pragma unroll
            for (int ni = 0; ni < 4; ni++)
                *(float4*)(pout + mi * 16 + ni * 4) = *(const float4*)acc[mi][ni];
        __syncthreads();
        if (tid == 0) arrive(&g_cnt[C_BAND + nt][0]);

        // phase 5: wait partials of my band (RAW) + sigh readers done (WAR)
        if (tid == 0)  pollge(&g_cnt[C_BAND + nt][0], 8u * (unsigned)(t + 1));
        if (tid == 32) pollge(&g_cnt[C_STAGE + my_chunk][0], 16u * (unsigned)(t + 1));
        __syncthreads();

        // phase 6: fused Euler update (h in registers)
        float4 v;
        {
            float4 s0 = *(const float4*)(g_part + f);
            float4 s1 = *(const float4*)(g_part + (size_t)BH + f);
            float4 s2 = *(const float4*)(g_part + (size_t)2 * BH + f);
            float4 s3 = *(const float4*)(g_part + (size_t)3 * BH + f);
            float4 s4 = *(const float4*)(g_part + (size_t)4 * BH + f);
            float4 s5 = *(const float4*)(g_part + (size_t)5 * BH + f);
            float4 s6 = *(const float4*)(g_part + (size_t)6 * BH + f);
            float4 s7 = *(const float4*)(g_part + (size_t)7 * BH + f);
            v.x = 0.9f * hp.x + 0.1f * (s0.x + s1.x + s2.x + s3.x + s4.x + s5.x + s6.x + s7.x + x0.x);
            v.y = 0.9f * hp.y + 0.1f * (s0.y + s1.y + s2.y + s3.y + s4.y + s5.y + s6.y + s7.y + x0.y);
            v.z = 0.9f * hp.z + 0.1f * (s0.z + s1.z + s2.z + s3.z + s4.z + s5.z + s6.z + s7.z + x1.x);
            v.w = 0.9f * hp.w + 0.1f * (s0.w + s1.w + s2.w + s3.w + s4.w + s5.w + s6.w + s7.w + x1.y);
            hp = v;
            g_sigh[(size_t)(b + 0) * NH + h] = __float2half_rn(sigmoidf_(v.x));
            g_sigh[(size_t)(b + 1) * NH + h] = __float2half_rn(sigmoidf_(v.y));
            g_sigh[(size_t)(b + 0) * NH + h + 8] = __float2half_rn(sigmoidf_(v.z));
            g_sigh[(size_t)(b + 1) * NH + h + 8] = __float2half_rn(sigmoidf_(v.w));
        }
        __syncthreads();
        if (tid == 0) {
            arrive(&g_cnt[C_PREAD + nt][0]);       // partials consumed
            arrive(&g_cnt[C_CHUNK + my_chunk][0]); // sigh(t+1) published
        }

        // phase 7: hidden stores (off critical path; consumed only by k_out)
        __stcs(hid0 + (size_t)t * NH, v.x);
        __stcs(hid1 + (size_t)t * NH, v.y);
        __stcs(hid0 + (size_t)t * NH + 8, v.z);
        __stcs(hid1 + (size_t)t * NH + 8, v.w);
    }

    flag_barrier(0);   // restore flag/slot state to 0
}

// ---------------- k_xw (HMMA): xwn[t][h][b] = x_t @ W_ih^T + 0.1*noise ----------------
__global__ void __launch_bounds__(256)
k_xw(const float* __restrict__ x, const float* __restrict__ noise) {
    extern __shared__ __align__(1024) char sm[];
    const uint32_t smb = smem_u32(sm);
    float* noise_s = (float*)(sm + X_NS);
    const int tid = threadIdx.x;
    const int wid = tid >> 5;
    const int lane = tid & 31;
    const int h0 = blockIdx.x * 128;
    const int t  = blockIdx.y;

    const int warp_m0 = (wid >> 1) * 32;
    const int warp_n0 = (wid & 1) * 32;
    const uint32_t aA = smb + X_W +
        (uint32_t)((warp_m0 + (lane & 15)) * PITCH + ((lane >> 4) << 4));
    const uint32_t bA = smb + X_B +
        (uint32_t)((warp_n0 + (lane & 7) + ((lane >> 4) << 3)) * PITCH +
                   (((lane >> 3) & 1) << 4));

#pragma unroll
    for (int it = 0; it < 8; it++) {
        const int b = it * 8 + wid;
        float4 nv = *(const float4*)(noise + (size_t)t * BH + (size_t)b * NH + h0 + lane * 4);
        *(float4*)(noise_s + b * 132 + lane * 4) = nv;
    }

    float acc[2][4][4];
#pragma unroll
    for (int mi = 0; mi < 2; mi++)
#pragma unroll
        for (int ni = 0; ni < 4; ni++)
#pragma unroll
            for (int j = 0; j < 4; j++) acc[mi][ni][j] = 0.0f;

    for (int c = 0; c < 2; c++) {
        for (int it = 0; it < 16; it++) {
            const int r = it * 8 + wid;
            uint4 hv = *(const uint4*)(g_wih + (size_t)(h0 + r) * NI + c * 256 + lane * 8);
            *(uint4*)(sm + X_W + r * PITCH + lane * 16) = hv;
        }
#pragma unroll
        for (int it = 0; it < 8; it++) {
            const int b = it * 8 + wid;
            const float* xr = x + ((size_t)b * NS + t) * NI + c * 256 + lane * 8;
            float4 v0 = *(const float4*)(xr);
            float4 v1 = *(const float4*)(xr + 4);
            uint4 hv = make_uint4(h2pack(v0.x, v0.y), h2pack(v0.z, v0.w),
                                  h2pack(v1.x, v1.y), h2pack(v1.z, v1.w));
            *(uint4*)(sm + X_B + b * PITCH + lane * 16) = hv;
        }
        __syncthreads();
        gemm16(acc, aA, bA);
        __syncthreads();
    }

    const int rq = lane >> 2;
    const int cq = (lane & 3) * 2;
#pragma unroll
    for (int mi = 0; mi < 2; mi++) {
        const int hl = warp_m0 + mi * 16 + rq;
#pragma unroll
        for (int ni = 0; ni < 4; ni++) {
            const int b = warp_n0 + ni * 8 + cq;
            float2 v0;
            v0.x = acc[mi][ni][0] + 0.1f * noise_s[(b + 0) * 132 + hl];
            v0.y = acc[mi][ni][1] + 0.1f * noise_s[(b + 1) * 132 + hl];
            *(float2*)(g_xwn + (size_t)t * BH + (size_t)(h0 + hl) * 64 + b) = v0;
            float2 v1;
            v1.x = acc[mi][ni][2] + 0.1f * noise_s[(b + 0) * 132 + hl + 8];
            v1.y = acc[mi][ni][3] + 0.1f * noise_s[(b + 1) * 132 + hl + 8];
            *(float2*)(g_xwn + (size_t)t * BH + (size_t)(h0 + hl + 8) * 64 + b) = v1;
        }
    }
}

// ---------------- k_out (HMMA): out = sigmoid(hidden) @ W_ho^T + b_ho ----------------
__global__ void __launch_bounds__(256)
k_out(const float* __restrict__ hidden, const float* __restrict__ bho,
      float* __restrict__ outp) {
    extern __shared__ __align__(1024) char sm[];
    const uint32_t smb = smem_u32(sm);
    const int tid = threadIdx.x;
    const int wid = tid >> 5;
    const int lane = tid & 31;
    const int o0 = blockIdx.x * 128;
    const int m0 = blockIdx.y * 64;

    const int warp_m0 = (wid >> 1) * 32;
    const int warp_n0 = (wid & 1) * 32;
    const uint32_t aA = smb + O_W +
        (uint32_t)((warp_m0 + (lane & 15)) * PITCH + ((lane >> 4) << 4));
    const uint32_t bA = smb + O_B +
        (uint32_t)((warp_n0 + (lane & 7) + ((lane >> 4) << 3)) * PITCH +
                   (((lane >> 3) & 1) << 4));

    float acc[2][4][4];
#pragma unroll
    for (int mi = 0; mi < 2; mi++)
#pragma unroll
        for (int ni = 0; ni < 4; ni++)
#pragma unroll
            for (int j = 0; j < 4; j++) acc[mi][ni][j] = 0.0f;

    for (int c = 0; c < 8; c++) {
        for (int it = 0; it < 16; it++) {
            const int r = it * 8 + wid;
            uint4 hv = *(const uint4*)(g_who + (size_t)(o0 + r) * NH + c * 256 + lane * 8);
            *(uint4*)(sm + O_W + r * PITCH + lane * 16) = hv;
        }
#pragma unroll
        for (int it = 0; it < 8; it++) {
            const int m = it * 8 + wid;
            const float* hr = hidden + (size_t)(m0 + m) * NH + c * 256 + lane * 8;
            float4 v0 = *(const float4*)(hr);
            float4 v1 = *(const float4*)(hr + 4);
            uint4 hv = make_uint4(
                h2pack(sigmoidf_(v0.x), sigmoidf_(v0.y)),
                h2pack(sigmoidf_(v0.z), sigmoidf_(v0.w)),
                h2pack(sigmoidf_(v1.x), sigmoidf_(v1.y)),
                h2pack(sigmoidf_(v1.z), sigmoidf_(v1.w)));
            *(uint4*)(sm + O_B + m * PITCH + lane * 16) = hv;
        }
        __syncthreads();
        gemm16(acc, aA, bA);
        __syncthreads();
    }

    const int rq = lane >> 2;
    const int cq = (lane & 3) * 2;
#pragma unroll
    for (int mi = 0; mi < 2; mi++) {
        const int o = o0 + warp_m0 + mi * 16 + rq;
        const float bv0 = bho[o];
        const float bv8 = bho[o + 8];
#pragma unroll
        for (int ni = 0; ni < 4; ni++) {
            const int m = m0 + warp_n0 + ni * 8 + cq;
            outp[(size_t)(m + 0) * NO + o] = acc[mi][ni][0] + bv0;
            outp[(size_t)(m + 1) * NO + o] = acc[mi][ni][1] + bv0;
            outp[(size_t)(m + 0) * NO + o + 8] = acc[mi][ni][2] + bv8;
            outp[(size_t)(m + 1) * NO + o + 8] = acc[mi][ni][3] + bv8;
        }
    }
}

extern "C" void kernel_launch(void* const* d_in, const int* in_sizes, int n_in,
                              void* d_out, int out_size) {
    const float* x     = (const float*)d_in[0];   // [B,S,I]
    const float* h0    = (const float*)d_in[1];   // [B,1,H]
    const float* Wih   = (const float*)d_in[2];   // [H,I]
    const float* Whh   = (const float*)d_in[3];   // [H,H]
    const float* Who   = (const float*)d_in[4];   // [O,H]
    const float* bho   = (const float*)d_in[5];   // [O]
    const float* noise = (const float*)d_in[6];   // [S,B,1,H]
    float* outp = (float*)d_out;

    const size_t OUTE = (size_t)NB * NS * NO;
    const size_t HIDE = (size_t)NB * NS * NH;

    float* hidden;
    if ((size_t)out_size >= OUTE + HIDE) {
        hidden = outp + OUTE;   // harness output = concat(out, hidden)
    } else {
        void* p = nullptr;
        cudaGetSymbolAddress(&p, g_hid_fb);
        hidden = (float*)p;
    }

    cudaFuncSetAttribute(k_recur, cudaFuncAttributeMaxDynamicSharedMemorySize, R_TOTAL);
    cudaFuncSetAttribute(k_xw, cudaFuncAttributeMaxDynamicSharedMemorySize, X_TOTAL);
    cudaFuncSetAttribute(k_out, cudaFuncAttributeMaxDynamicSharedMemorySize, O_TOTAL);

    // 0. one-time weight conversion (fp32 -> fp16)
    k_convW<<<(NH * NI + NO * NH) / 256, 256>>>(Wih, Who);

    // 1. input projection (HMMA) + noise fold, layout [t][h][b]
    k_xw<<<dim3(NH / 128, NS), 256, X_TOTAL>>>(x, noise);

    // 2. full recurrence: persistent HMMA kernel, sparse cross-block sync
    k_recur<<<GB, 256, R_TOTAL>>>(h0, Whh, hidden);

    // 3. output projection (HMMA)
    k_out<<<dim3(NO / 128, (NB * NS) / 64), 256, O_TOTAL>>>(hidden, bho, outp);
}

// round 10
// speedup vs baseline: 3.8242x; 1.1151x over previous
#include <cuda_runtime.h>
#include <cuda_fp16.h>
#include <cstdint>

// ---------------- problem constants ----------------
namespace {
constexpr int NB = 64;     // batch
constexpr int NS = 1024;   // sequence length
constexpr int NI = 512;    // input dim
constexpr int NH = 2048;   // hidden dim
constexpr int NO = 512;    // output dim
constexpr int BH = NB * NH;      // 131072 state elements

constexpr int GB = 128;          // persistent blocks (1/SM, co-resident)
constexpr int SK = 4;            // split-K chunks = cluster size
constexpr int KC = NH / SK;      // 512 K per recurrence block
constexpr int NT = 32;           // bands of 64 h-rows

// k_recur smem: K=512 fp16 rows (1024B) + 16B pad
constexpr int PITCH2 = 1040;
constexpr int R_W = 0;                        // 64 rows (W chunk)
constexpr int R_B = R_W + 64 * PITCH2;        // 64 rows (sigh chunk)
constexpr int R_TOTAL = R_B + 64 * PITCH2;    // 133120 B

// projection kernels: K=256 rows (512B) + 16B pad
constexpr int PITCH = 528;
constexpr int X_W  = 0;
constexpr int X_B  = X_W + 128 * PITCH;
constexpr int X_NS = X_B + 64 * PITCH;
constexpr int X_TOTAL = X_NS + 64 * 132 * 4;
constexpr int O_W = 0;
constexpr int O_B = O_W + 128 * PITCH;
constexpr int O_TOTAL = O_B + 64 * PITCH;

// counters: rows 0-3 chunk (sigh published), 4-7 stage (sigh consumed)
constexpr int C_CHUNK = 0;
constexpr int C_STAGE = 4;
}

// ---------------- scratch (static device allocations) ----------------
__device__ float g_xwn[(size_t)NS * NB * NH];     // [t][h][b] xw + 0.1*noise
__device__ float g_hid_fb[(size_t)NB * NS * NH];  // fallback hidden storage
__device__ float g_part[(size_t)SK * BH];         // partials [sk][band nt][writer-contig 4096]
__device__ __half g_sigh[BH];                     // sigmoid(h) fp16 [b][h]
__device__ __half g_wih[(size_t)NH * NI];         // W_ih fp16 [h][i]
__device__ __half g_who[(size_t)NO * NH];         // W_ho fp16 [o][h]

// sync state
__device__ unsigned g_slots[GB];
__device__ unsigned g_flag;
__device__ unsigned g_cnt[8][8];   // 32B-strided monotonic counters

// ---------------- helpers ----------------
__device__ __forceinline__ float sigmoidf_(float x) {
    return 1.0f / (1.0f + __expf(-x));
}
__device__ __forceinline__ unsigned h2pack(float a, float b) {
    __half2 t;
    t.x = __float2half_rn(a);
    t.y = __float2half_rn(b);
    return *reinterpret_cast<unsigned*>(&t);
}
__device__ __forceinline__ uint32_t smem_u32(const void* p) {
    uint32_t a;
    asm("{ .reg .u64 t; cvta.to.shared.u64 t, %1; cvt.u32.u64 %0, t; }"
        : "=r"(a) : "l"(p));
    return a;
}
__device__ __forceinline__ void ldsm4(unsigned* r, uint32_t addr) {
    asm volatile("ldmatrix.sync.aligned.m8n8.x4.shared.b16 {%0,%1,%2,%3}, [%4];"
                 : "=r"(r[0]), "=r"(r[1]), "=r"(r[2]), "=r"(r[3]) : "r"(addr));
}
__device__ __forceinline__ void mma_f16(float* d, const unsigned* a, const unsigned* b) {
    asm("mma.sync.aligned.m16n8k16.row.col.f32.f16.f16.f32 "
        "{%0,%1,%2,%3}, {%4,%5,%6,%7}, {%8,%9}, {%0,%1,%2,%3};"
        : "+f"(d[0]), "+f"(d[1]), "+f"(d[2]), "+f"(d[3])
        : "r"(a[0]), "r"(a[1]), "r"(a[2]), "r"(a[3]), "r"(b[0]), "r"(b[1]));
}

// ---------------- sync primitives ----------------
__device__ __forceinline__ void arrive(unsigned* p) {
    asm volatile("red.release.gpu.global.add.u32 [%0], %1;"
                 :: "l"(p), "r"(1u) : "memory");
}
__device__ __forceinline__ void pollge(unsigned* p, unsigned target) {
    unsigned v;
    do {
        asm volatile("ld.acquire.gpu.global.u32 %0, [%1];"
                     : "=r"(v) : "l"(p) : "memory");
    } while (v < target);
}
__device__ __forceinline__ void cluster_arrive_() {
    asm volatile("barrier.cluster.arrive.aligned;" ::: "memory");
}
__device__ __forceinline__ void cluster_wait_() {
    asm volatile("barrier.cluster.wait.aligned;" ::: "memory");
}

// flag-array full barrier (used twice per launch; state returns to 0)
__device__ __forceinline__ void flag_barrier(unsigned want) {
    __syncthreads();
    if (threadIdx.x == 0) {
        asm volatile("st.release.gpu.global.u32 [%0], %1;"
                     :: "l"(&g_slots[blockIdx.x]), "r"(want) : "memory");
    }
    if (blockIdx.x == 0) {
        if (threadIdx.x < GB) {
            unsigned v;
            do {
                asm volatile("ld.acquire.gpu.global.u32 %0, [%1];"
                             : "=r"(v) : "l"(&g_slots[threadIdx.x]) : "memory");
            } while (v != want);
        }
        __syncthreads();
        if (threadIdx.x == 0) {
            asm volatile("st.release.gpu.global.u32 [%0], %1;"
                         :: "l"(&g_flag), "r"(want) : "memory");
        }
    } else {
        if (threadIdx.x == 0) {
            unsigned v;
            do {
                asm volatile("ld.acquire.gpu.global.u32 %0, [%1];"
                             : "=r"(v) : "l"(&g_flag) : "memory");
            } while (v != want);
        }
        __syncthreads();
    }
}

// ---------------- W_ih / W_ho fp32 -> fp16 conversion (one-time) ----------------
__global__ void __launch_bounds__(256) k_convW(const float* __restrict__ Wih,
                                               const float* __restrict__ Who) {
    const int idx = blockIdx.x * 256 + threadIdx.x;
    if (idx < NH * NI) {
        g_wih[idx] = __float2half_rn(Wih[idx]);
    } else {
        int i = idx - NH * NI;
        g_who[i] = __float2half_rn(Who[i]);
    }
}

// ---------------- persistent recurrence kernel (4-CTA band clusters) ----------------
// Cluster nt = 4 CTAs (sk=0..3); CTA computes D[64 h, 64 b] over K chunk 512,
// partials exchanged via L2 + cluster barrier; update split across the cluster.
__global__ void __launch_bounds__(256, 1) __cluster_dims__(SK, 1, 1)
k_recur(const float* __restrict__ h0, const float* __restrict__ Whh,
        float* __restrict__ hidden) {
    extern __shared__ __align__(1024) char sm[];
    const uint32_t smb = smem_u32(sm);
    const int tid = threadIdx.x;
    const int wid = tid >> 5;
    const int lane = tid & 31;
    const int bx = blockIdx.x;
    const int nt = bx >> 2;            // band 0..31 (cluster id)
    const int sk = bx & 3;             // k-chunk / cluster rank
    const int n0 = nt * 64;
    const int kbeg = sk * KC;
    const int myc = nt >> 3;           // chunk this band's sigh feeds

    if (bx == 0 && tid < 8) g_cnt[tid][0] = 0;

    // ---- one-time: stage W_hh chunk [64 rows x 512 k] fp16 into SMEM ----
    for (int it = 0; it < 8; it++) {
        const int r = it * 8 + wid;
        const float* wr = Whh + (size_t)(n0 + r) * NH + kbeg;
#pragma unroll
        for (int g = 0; g < 2; g++) {
            const int c = g * 256 + lane * 8;
            float4 v0 = *(const float4*)(wr + c);
            float4 v1 = *(const float4*)(wr + c + 4);
            uint4 H = make_uint4(h2pack(v0.x, v0.y), h2pack(v0.z, v0.w),
                                 h2pack(v1.x, v1.y), h2pack(v1.z, v1.w));
            *(uint4*)(sm + R_W + r * PITCH2 + c * 2) = H;
        }
    }

    // ---- update mapping: CTA sk updates band slice fb = sk*1024 + tid*4 ----
    const int fb = (sk << 10) + (tid << 2);
    const int w = fb >> 4, q = (fb & 15) >> 2;
    const int mi_u = q >> 1, ni_u = q & 1;
    const int wwid = w >> 5, wlane = w & 31;
    const int hl = ((wwid >> 2) << 5) + mi_u * 16 + (wlane >> 2);
    const int b  = ((wwid & 3) << 4) + ni_u * 8 + ((wlane & 3) << 1);
    const int h  = n0 + hl;   // thread owns (h,b),(h,b+1),(h+8,b),(h+8,b+1)

    // ---- init state: h in registers, sigh fp16 [b][h] ----
    float4 hp;
    hp.x = h0[(size_t)(b + 0) * NH + h];
    hp.y = h0[(size_t)(b + 1) * NH + h];
    hp.z = h0[(size_t)(b + 0) * NH + h + 8];
    hp.w = h0[(size_t)(b + 1) * NH + h + 8];
    g_sigh[(size_t)(b + 0) * NH + h] = __float2half_rn(sigmoidf_(hp.x));
    g_sigh[(size_t)(b + 1) * NH + h] = __float2half_rn(sigmoidf_(hp.y));
    g_sigh[(size_t)(b + 0) * NH + h + 8] = __float2half_rn(sigmoidf_(hp.z));
    g_sigh[(size_t)(b + 1) * NH + h + 8] = __float2half_rn(sigmoidf_(hp.w));

    flag_barrier(1);      // counter reset + init sigh visible
    cluster_arrive_();    // arm first in-loop cluster wait

    // ---- GEMM constants: warp tile m32 x n16 ----
    const int warp_m0 = (wid >> 2) << 5;     // 0 / 32
    const int warp_n0 = (wid & 3) << 4;      // 0,16,32,48
    const uint32_t aA = smb + R_W +
        (uint32_t)((warp_m0 + (lane & 15)) * PITCH2 + ((lane >> 4) << 4));
    const uint32_t bA = smb + R_B +
        (uint32_t)((warp_n0 + (lane & 7) + ((lane >> 4) << 3)) * PITCH2 +
                   (((lane >> 3) & 1) << 4));

    float* pout = g_part + (size_t)sk * BH + (size_t)nt * 4096 + tid * 16;
    const float* pband = g_part + (size_t)nt * 4096;
    float* hid0 = hidden + (size_t)(b + 0) * NS * NH + h;
    float* hid1 = hidden + (size_t)(b + 1) * NS * NH + h;

    for (int t = 0; t < NS; t++) {
        // prefetch update-phase xw operands (hide DRAM latency behind GEMM)
        const float2 x0 = __ldcs((const float2*)(g_xwn + (size_t)t * BH + (size_t)h * 64 + b));
        const float2 x1 = __ldcs((const float2*)(g_xwn + (size_t)t * BH + (size_t)(h + 8) * 64 + b));

        // wait sigh(t) chunk published (32 updater CTAs per chunk)
        if (tid == 0) pollge(&g_cnt[C_CHUNK + sk][0], 32u * (unsigned)t);
        __syncthreads();

        // stage sigh chunk [64 b rows x 512 k] fp16 into SMEM
#pragma unroll
        for (int it = 0; it < 8; it++) {
            const int r = it * 8 + wid;
            const uint4* src = (const uint4*)(g_sigh + (size_t)r * NH + kbeg) + lane * 2;
            uint4 v0 = src[0];
            uint4 v1 = src[1];
            *(uint4*)(sm + R_B + r * PITCH2 + lane * 32) = v0;
            *(uint4*)(sm + R_B + r * PITCH2 + lane * 32 + 16) = v1;
        }
        __syncthreads();
        if (tid == 0) arrive(&g_cnt[C_STAGE + sk][0]);   // done reading sigh(t)

        // GEMM m64n64k512: 32 k-steps x (3 ldsm4 + 4 MMA)
        float acc[2][2][4];
#pragma unroll
        for (int mi = 0; mi < 2; mi++)
#pragma unroll
            for (int ni = 0; ni < 2; ni++)
#pragma unroll
                for (int j = 0; j < 4; j++) acc[mi][ni][j] = 0.0f;

#pragma unroll 4
        for (int ks = 0; ks < 32; ks++) {
            const uint32_t ko = ks * 32;
            unsigned am[2][4], bm[2][2];
            ldsm4(am[0], aA + ko);
            ldsm4(am[1], aA + 16 * PITCH2 + ko);
            ldsm4(&bm[0][0], bA + ko);
#pragma unroll
            for (int mi = 0; mi < 2; mi++)
#pragma unroll
                for (int ni = 0; ni < 2; ni++)
                    mma_f16(acc[mi][ni], am[mi], bm[ni]);
        }

        // WAR: peers finished reading previous partials
        cluster_wait_();

        // store partials (thread-contiguous, coalesced)
#pragma unroll
        for (int qd = 0; qd < 4; qd++)
            *(float4*)(pout + qd * 4) = *(const float4*)acc[qd >> 1][qd & 1];
        cluster_arrive_();   // partials written (release)
        cluster_wait_();     // all 4 CTAs' partials visible (acquire)

        // read partials for my update slice
        float4 s0 = *(const float4*)(pband + fb);
        float4 s1 = *(const float4*)(pband + (size_t)BH + fb);
        float4 s2 = *(const float4*)(pband + (size_t)2 * BH + fb);
        float4 s3 = *(const float4*)(pband + (size_t)3 * BH + fb);
        cluster_arrive_();   // partials consumed (arms next step's WAR wait)

        // fused Euler update
        float4 v;
        v.x = 0.9f * hp.x + 0.1f * (s0.x + s1.x + s2.x + s3.x + x0.x);
        v.y = 0.9f * hp.y + 0.1f * (s0.y + s1.y + s2.y + s3.y + x0.y);
        v.z = 0.9f * hp.z + 0.1f * (s0.z + s1.z + s2.z + s3.z + x1.x);
        v.w = 0.9f * hp.w + 0.1f * (s0.w + s1.w + s2.w + s3.w + x1.y);
        hp = v;

        // WAR: consumers of my sigh chunk finished staging step t
        if (tid == 0) pollge(&g_cnt[C_STAGE + myc][0], 32u * (unsigned)(t + 1));
        __syncthreads();

        g_sigh[(size_t)(b + 0) * NH + h] = __float2half_rn(sigmoidf_(v.x));
        g_sigh[(size_t)(b + 1) * NH + h] = __float2half_rn(sigmoidf_(v.y));
        g_sigh[(size_t)(b + 0) * NH + h + 8] = __float2half_rn(sigmoidf_(v.z));
        g_sigh[(size_t)(b + 1) * NH + h + 8] = __float2half_rn(sigmoidf_(v.w));
        __syncthreads();
        if (tid == 0) arrive(&g_cnt[C_CHUNK + myc][0]);  // sigh(t+1) published

        // hidden stores (off critical path; consumed only by k_out)
        __stcs(hid0 + (size_t)t * NH, v.x);
        __stcs(hid1 + (size_t)t * NH, v.y);
        __stcs(hid0 + (size_t)t * NH + 8, v.z);
        __stcs(hid1 + (size_t)t * NH + 8, v.w);
    }

    cluster_wait_();     // balance final arrive
    flag_barrier(0);     // restore flag/slot state
}

// ---------------- k_xw (HMMA): xwn[t][h][b] = x_t @ W_ih^T + 0.1*noise ----------------
__global__ void __launch_bounds__(256)
k_xw(const float* __restrict__ x, const float* __restrict__ noise) {
    extern __shared__ __align__(1024) char sm[];
    const uint32_t smb = smem_u32(sm);
    float* noise_s = (float*)(sm + X_NS);
    const int tid = threadIdx.x;
    const int wid = tid >> 5;
    const int lane = tid & 31;
    const int h0 = blockIdx.x * 128;
    const int t  = blockIdx.y;

    const int warp_m0 = (wid >> 1) * 32;
    const int warp_n0 = (wid & 1) * 32;
    const uint32_t aA = smb + X_W +
        (uint32_t)((warp_m0 + (lane & 15)) * PITCH + ((lane >> 4) << 4));
    const uint32_t bA = smb + X_B +
        (uint32_t)((warp_n0 + (lane & 7) + ((lane >> 4) << 3)) * PITCH +
                   (((lane >> 3) & 1) << 4));

#pragma unroll
    for (int it = 0; it < 8; it++) {
        const int b = it * 8 + wid;
        float4 nv = *(const float4*)(noise + (size_t)t * BH + (size_t)b * NH + h0 + lane * 4);
        *(float4*)(noise_s + b * 132 + lane * 4) = nv;
    }

    float acc[2][4][4];
#pragma unroll
    for (int mi = 0; mi < 2; mi++)
#pragma unroll
        for (int ni = 0; ni < 4; ni++)
#pragma unroll
            for (int j = 0; j < 4; j++) acc[mi][ni][j] = 0.0f;

    for (int c = 0; c < 2; c++) {
        for (int it = 0; it < 16; it++) {
            const int r = it * 8 + wid;
            uint4 hv = *(const uint4*)(g_wih + (size_t)(h0 + r) * NI + c * 256 + lane * 8);
            *(uint4*)(sm + X_W + r * PITCH + lane * 16) = hv;
        }
#pragma unroll
        for (int it = 0; it < 8; it++) {
            const int b = it * 8 + wid;
            const float* xr = x + ((size_t)b * NS + t) * NI + c * 256 + lane * 8;
            float4 v0 = *(const float4*)(xr);
            float4 v1 = *(const float4*)(xr + 4);
            uint4 hv = make_uint4(h2pack(v0.x, v0.y), h2pack(v0.z, v0.w),
                                  h2pack(v1.x, v1.y), h2pack(v1.z, v1.w));
            *(uint4*)(sm + X_B + b * PITCH + lane * 16) = hv;
        }
        __syncthreads();
#pragma unroll 4
        for (int ks = 0; ks < 16; ks++) {
            const uint32_t ko = ks * 32;
            unsigned am[2][4], bm[4][2];
            ldsm4(am[0], aA + ko);
            ldsm4(am[1], aA + ko + 16 * PITCH);
            ldsm4(&bm[0][0], bA + ko);
            ldsm4(&bm[2][0], bA + ko + 16 * PITCH);
#pragma unroll
            for (int mi = 0; mi < 2; mi++)
#pragma unroll
                for (int ni = 0; ni < 4; ni++)
                    mma_f16(acc[mi][ni], am[mi], bm[ni]);
        }
        __syncthreads();
    }

    const int rq = lane >> 2;
    const int cq = (lane & 3) * 2;
#pragma unroll
    for (int mi = 0; mi < 2; mi++) {
        const int hl = warp_m0 + mi * 16 + rq;
#pragma unroll
        for (int ni = 0; ni < 4; ni++) {
            const int b = warp_n0 + ni * 8 + cq;
            float2 v0;
            v0.x = acc[mi][ni][0] + 0.1f * noise_s[(b + 0) * 132 + hl];
            v0.y = acc[mi][ni][1] + 0.1f * noise_s[(b + 1) * 132 + hl];
            *(float2*)(g_xwn + (size_t)t * BH + (size_t)(h0 + hl) * 64 + b) = v0;
            float2 v1;
            v1.x = acc[mi][ni][2] + 0.1f * noise_s[(b + 0) * 132 + hl + 8];
            v1.y = acc[mi][ni][3] + 0.1f * noise_s[(b + 1) * 132 + hl + 8];
            *(float2*)(g_xwn + (size_t)t * BH + (size_t)(h0 + hl + 8) * 64 + b) = v1;
        }
    }
}

// ---------------- k_out (HMMA): out = sigmoid(hidden) @ W_ho^T + b_ho ----------------
__global__ void __launch_bounds__(256)
k_out(const float* __restrict__ hidden, const float* __restrict__ bho,
      float* __restrict__ outp) {
    extern __shared__ __align__(1024) char sm[];
    const uint32_t smb = smem_u32(sm);
    const int tid = threadIdx.x;
    const int wid = tid >> 5;
    const int lane = tid & 31;
    const int o0 = blockIdx.x * 128;
    const int m0 = blockIdx.y * 64;

    const int warp_m0 = (wid >> 1) * 32;
    const int warp_n0 = (wid & 1) * 32;
    const uint32_t aA = smb + O_W +
        (uint32_t)((warp_m0 + (lane & 15)) * PITCH + ((lane >> 4) << 4));
    const uint32_t bA = smb + O_B +
        (uint32_t)((warp_n0 + (lane & 7) + ((lane >> 4) << 3)) * PITCH +
                   (((lane >> 3) & 1) << 4));

    float acc[2][4][4];
#pragma unroll
    for (int mi = 0; mi < 2; mi++)
#pragma unroll
        for (int ni = 0; ni < 4; ni++)
#pragma unroll
            for (int j = 0; j < 4; j++) acc[mi][ni][j] = 0.0f;

    for (int c = 0; c < 8; c++) {
        for (int it = 0; it < 16; it++) {
            const int r = it * 8 + wid;
            uint4 hv = *(const uint4*)(g_who + (size_t)(o0 + r) * NH + c * 256 + lane * 8);
            *(uint4*)(sm + O_W + r * PITCH + lane * 16) = hv;
        }
#pragma unroll
        for (int it = 0; it < 8; it++) {
            const int m = it * 8 + wid;
            const float* hr = hidden + (size_t)(m0 + m) * NH + c * 256 + lane * 8;
            float4 v0 = *(const float4*)(hr);
            float4 v1 = *(const float4*)(hr + 4);
            uint4 hv = make_uint4(
                h2pack(sigmoidf_(v0.x), sigmoidf_(v0.y)),
                h2pack(sigmoidf_(v0.z), sigmoidf_(v0.w)),
                h2pack(sigmoidf_(v1.x), sigmoidf_(v1.y)),
                h2pack(sigmoidf_(v1.z), sigmoidf_(v1.w)));
            *(uint4*)(sm + O_B + m * PITCH + lane * 16) = hv;
        }
        __syncthreads();
#pragma unroll 4
        for (int ks = 0; ks < 16; ks++) {
            const uint32_t ko = ks * 32;
            unsigned am[2][4], bm[4][2];
            ldsm4(am[0], aA + ko);
            ldsm4(am[1], aA + ko + 16 * PITCH);
            ldsm4(&bm[0][0], bA + ko);
            ldsm4(&bm[2][0], bA + ko + 16 * PITCH);
#pragma unroll
            for (int mi = 0; mi < 2; mi++)
#pragma unroll
                for (int ni = 0; ni < 4; ni++)
                    mma_f16(acc[mi][ni], am[mi], bm[ni]);
        }
        __syncthreads();
    }

    const int rq = lane >> 2;
    const int cq = (lane & 3) * 2;
#pragma unroll
    for (int mi = 0; mi < 2; mi++) {
        const int o = o0 + warp_m0 + mi * 16 + rq;
        const float bv0 = bho[o];
        const float bv8 = bho[o + 8];
#pragma unroll
        for (int ni = 0; ni < 4; ni++) {
            const int m = m0 + warp_n0 + ni * 8 + cq;
            outp[(size_t)(m + 0) * NO + o] = acc[mi][ni][0] + bv0;
            outp[(size_t)(m + 1) * NO + o] = acc[mi][ni][1] + bv0;
            outp[(size_t)(m + 0) * NO + o + 8] = acc[mi][ni][2] + bv8;
            outp[(size_t)(m + 1) * NO + o + 8] = acc[mi][ni][3] + bv8;
        }
    }
}

extern "C" void kernel_launch(void* const* d_in, const int* in_sizes, int n_in,
                              void* d_out, int out_size) {
    const float* x     = (const float*)d_in[0];   // [B,S,I]
    const float* h0    = (const float*)d_in[1];   // [B,1,H]
    const float* Wih   = (const float*)d_in[2];   // [H,I]
    const float* Whh   = (const float*)d_in[3];   // [H,H]
    const float* Who   = (const float*)d_in[4];   // [O,H]
    const float* bho   = (const float*)d_in[5];   // [O]
    const float* noise = (const float*)d_in[6];   // [S,B,1,H]
    float* outp = (float*)d_out;

    const size_t OUTE = (size_t)NB * NS * NO;
    const size_t HIDE = (size_t)NB * NS * NH;

    float* hidden;
    if ((size_t)out_size >= OUTE + HIDE) {
        hidden = outp + OUTE;   // harness output = concat(out, hidden)
    } else {
        void* p = nullptr;
        cudaGetSymbolAddress(&p, g_hid_fb);
        hidden = (float*)p;
    }

    cudaFuncSetAttribute(k_recur, cudaFuncAttributeMaxDynamicSharedMemorySize, R_TOTAL);
    cudaFuncSetAttribute(k_xw, cudaFuncAttributeMaxDynamicSharedMemorySize, X_TOTAL);
    cudaFuncSetAttribute(k_out, cudaFuncAttributeMaxDynamicSharedMemorySize, O_TOTAL);

    // 0. one-time weight conversion (fp32 -> fp16)
    k_convW<<<(NH * NI + NO * NH) / 256, 256>>>(Wih, Who);

    // 1. input projection (HMMA) + noise fold, layout [t][h][b]
    k_xw<<<dim3(NH / 128, NS), 256, X_TOTAL>>>(x, noise);

    // 2. full recurrence: persistent HMMA kernel, 4-CTA band clusters
    k_recur<<<GB, 256, R_TOTAL>>>(h0, Whh, hidden);

    // 3. output projection (HMMA)
    k_out<<<dim3(NO / 128, (NB * NS) / 64), 256, O_TOTAL>>>(hidden, bho, outp);
}